// round 5
// baseline (speedup 1.0000x reference)
#include <cuda_runtime.h>

#define BQ 4
#define LQ 1024
#define DD 1280
#define HH 20
#define DHD 64
#define BH (BQ*HH)          // 80
#define MTOT (BQ*LQ)        // 4096
#define ALPHA 0.48f
#define SCALE 0.125f        // 1/sqrt(64)

// Scratch (static device globals — allocation-free)
__device__ float g_q[BH*LQ*DHD];
__device__ float g_k[BH*LQ*DHD];
__device__ float g_v[BH*LQ*DHD];
__device__ float g_ctx[MTOT*DD];

// ---------------------------------------------------------------------------
// Tiled SGEMM 128x128x8, 256 threads, 8x8 micro-tile.
// ---------------------------------------------------------------------------

__global__ void __launch_bounds__(256) qkv_gemm(const float* __restrict__ X,
                                                const float* __restrict__ Wq,
                                                const float* __restrict__ Wk,
                                                const float* __restrict__ Wv) {
    __shared__ float As[8][132];   // transposed A tile [k][m], padded
    __shared__ float Bs[8][128];

    const float* W = (blockIdx.z == 0) ? Wq : (blockIdx.z == 1) ? Wk : Wv;
    float* dst = (blockIdx.z == 0) ? g_q : (blockIdx.z == 1) ? g_k : g_v;

    const int t  = threadIdx.x;
    const int ty = t >> 4, tx = t & 15;
    const int bm = blockIdx.y * 128, bn = blockIdx.x * 128;

    const int a_row = t >> 1, a_k4 = (t & 1) * 4;
    const int b_k = t >> 5, b_n4 = (t & 31) * 4;

    const float* Aptr = X + (bm + a_row) * DD + a_k4;
    const float* Bptr = W + b_k * DD + bn + b_n4;

    float acc[8][8] = {};

    for (int k0 = 0; k0 < DD; k0 += 8) {
        float4 av = *(const float4*)(Aptr + k0);
        float4 bv = *(const float4*)(Bptr + (size_t)k0 * DD);
        As[a_k4 + 0][a_row] = av.x;
        As[a_k4 + 1][a_row] = av.y;
        As[a_k4 + 2][a_row] = av.z;
        As[a_k4 + 3][a_row] = av.w;
        *(float4*)&Bs[b_k][b_n4] = bv;
        __syncthreads();
        #pragma unroll
        for (int k = 0; k < 8; k++) {
            float a[8], b[8];
            *(float4*)(a)     = *(const float4*)&As[k][ty * 8];
            *(float4*)(a + 4) = *(const float4*)&As[k][ty * 8 + 4];
            *(float4*)(b)     = *(const float4*)&Bs[k][tx * 8];
            *(float4*)(b + 4) = *(const float4*)&Bs[k][tx * 8 + 4];
            #pragma unroll
            for (int i = 0; i < 8; i++)
                #pragma unroll
                for (int j = 0; j < 8; j++)
                    acc[i][j] += a[i] * b[j];
        }
        __syncthreads();
    }

    // Scatter into head-batch layout [B*H, L, DH]
    #pragma unroll
    for (int i = 0; i < 8; i++) {
        int m = bm + ty * 8 + i;
        int bb = m >> 10, lq = m & 1023;
        #pragma unroll
        for (int j = 0; j < 8; j++) {
            int n = bn + tx * 8 + j;
            int hh = n >> 6, dh = n & 63;
            dst[(((size_t)bb * HH + hh) * LQ + lq) * DHD + dh] = acc[i][j];
        }
    }
}

__global__ void __launch_bounds__(256) out_gemm(const float* __restrict__ Wo,
                                                const float* __restrict__ bo,
                                                float* __restrict__ out) {
    __shared__ float As[8][132];
    __shared__ float Bs[8][128];

    const int t  = threadIdx.x;
    const int ty = t >> 4, tx = t & 15;
    const int bm = blockIdx.y * 128, bn = blockIdx.x * 128;

    const int a_row = t >> 1, a_k4 = (t & 1) * 4;
    const int b_k = t >> 5, b_n4 = (t & 31) * 4;

    const float* Aptr = g_ctx + (size_t)(bm + a_row) * DD + a_k4;
    const float* Bptr = Wo + (size_t)b_k * DD + bn + b_n4;

    float acc[8][8] = {};

    for (int k0 = 0; k0 < DD; k0 += 8) {
        float4 av = *(const float4*)(Aptr + k0);
        float4 bv = *(const float4*)(Bptr + (size_t)k0 * DD);
        As[a_k4 + 0][a_row] = av.x;
        As[a_k4 + 1][a_row] = av.y;
        As[a_k4 + 2][a_row] = av.z;
        As[a_k4 + 3][a_row] = av.w;
        *(float4*)&Bs[b_k][b_n4] = bv;
        __syncthreads();
        #pragma unroll
        for (int k = 0; k < 8; k++) {
            float a[8], b[8];
            *(float4*)(a)     = *(const float4*)&As[k][ty * 8];
            *(float4*)(a + 4) = *(const float4*)&As[k][ty * 8 + 4];
            *(float4*)(b)     = *(const float4*)&Bs[k][tx * 8];
            *(float4*)(b + 4) = *(const float4*)&Bs[k][tx * 8 + 4];
            #pragma unroll
            for (int i = 0; i < 8; i++)
                #pragma unroll
                for (int j = 0; j < 8; j++)
                    acc[i][j] += a[i] * b[j];
        }
        __syncthreads();
    }

    #pragma unroll
    for (int i = 0; i < 8; i++) {
        int m = bm + ty * 8 + i;
        #pragma unroll
        for (int j = 0; j < 8; j++) {
            int n = bn + tx * 8 + j;
            out[(size_t)m * DD + n] = acc[i][j] + bo[n];
        }
    }
}

// ---------------------------------------------------------------------------
// Flash attention: per block one (bh, 64-query tile); KV length 2048
// (first 1024 = self K/V, second 1024 = ALPHA * background K/V).
// Q,K stored transposed [dh][row] with XOR swizzle: conflict-free LDS.128.
// ---------------------------------------------------------------------------

__device__ __forceinline__ void stsw(char* buf, int dh, int l, float v) {
    int off = (dh << 8) + (l << 2);
    off ^= ((off >> 10) & 7) << 4;
    *(float*)(buf + off) = v;
}
__device__ __forceinline__ float4 ldsw(const char* buf, int dh, int col4) {
    int off = (dh << 8) + (col4 << 2);
    off ^= ((off >> 10) & 7) << 4;
    return *(const float4*)(buf + off);
}

__global__ void __launch_bounds__(256) attn_kernel(const float* __restrict__ Kbg,
                                                   const float* __restrict__ Vbg) {
    extern __shared__ char smbase[];
    char*  Qb = smbase;                        // 16 KB, transposed+swizzled
    char*  Kb = smbase + 16384;                // 16 KB, transposed+swizzled
    float* Vs = (float*)(smbase + 32768);      // 16 KB, natural [kv][dh]
    float* Ps = (float*)(smbase + 49152);      // 16 KB, [q][kv]

    const int t  = threadIdx.x;
    const int i4 = (t >> 4) << 2;    // query-row base (0..60)
    const int j4 = (t & 15) << 2;    // kv-col / dh-col base (0..60)
    const int bh = blockIdx.y;
    const int q0 = blockIdx.x << 6;

    // Load Q tile transposed + swizzled
    {
        const float* Qg = g_q + ((size_t)bh * LQ + q0) * DHD;
        #pragma unroll
        for (int it = 0; it < 4; it++) {
            int fidx = t + (it << 8);
            int l = fidx >> 4;
            int dh4 = (fidx & 15) << 2;
            float4 v = *(const float4*)(Qg + l * DHD + dh4);
            stsw(Qb, dh4 + 0, l, v.x);
            stsw(Qb, dh4 + 1, l, v.y);
            stsw(Qb, dh4 + 2, l, v.z);
            stsw(Qb, dh4 + 3, l, v.w);
        }
    }

    float o[4][4] = {};
    float mrow[4] = {-1e30f, -1e30f, -1e30f, -1e30f};
    float lrow[4] = {};

    for (int tile = 0; tile < 32; tile++) {
        __syncthreads();   // prior O-update done reading Vs/Ps
        const int kv0 = tile << 6;
        const float *Ksrc, *Vsrc;
        float mult;
        if (kv0 < LQ) {
            Ksrc = g_k + ((size_t)bh * LQ + kv0) * DHD;
            Vsrc = g_v + ((size_t)bh * LQ + kv0) * DHD;
            mult = 1.0f;
        } else {
            Ksrc = Kbg + ((size_t)bh * LQ + (kv0 - LQ)) * DHD;
            Vsrc = Vbg + ((size_t)bh * LQ + (kv0 - LQ)) * DHD;
            mult = ALPHA;
        }
        #pragma unroll
        for (int it = 0; it < 4; it++) {
            int fidx = t + (it << 8);
            int l = fidx >> 4;
            int dh4 = (fidx & 15) << 2;
            float4 kv = *(const float4*)(Ksrc + l * DHD + dh4);
            stsw(Kb, dh4 + 0, l, kv.x * mult);
            stsw(Kb, dh4 + 1, l, kv.y * mult);
            stsw(Kb, dh4 + 2, l, kv.z * mult);
            stsw(Kb, dh4 + 3, l, kv.w * mult);
            float4 vv = *(const float4*)(Vsrc + l * DHD + dh4);
            vv.x *= mult; vv.y *= mult; vv.z *= mult; vv.w *= mult;
            *(float4*)&Vs[l * DHD + dh4] = vv;
        }
        __syncthreads();

        // S = Q K^T  (4x4 per thread)
        float s[4][4] = {};
        #pragma unroll 8
        for (int k = 0; k < 64; k++) {
            float4 qv = ldsw(Qb, k, i4);
            float4 kq = ldsw(Kb, k, j4);
            float qf[4] = {qv.x, qv.y, qv.z, qv.w};
            float kf[4] = {kq.x, kq.y, kq.z, kq.w};
            #pragma unroll
            for (int r = 0; r < 4; r++)
                #pragma unroll
                for (int c = 0; c < 4; c++)
                    s[r][c] += qf[r] * kf[c];
        }
        #pragma unroll
        for (int r = 0; r < 4; r++)
            #pragma unroll
            for (int c = 0; c < 4; c++)
                s[r][c] *= SCALE;

        // Online softmax: stats reduced across the 16 lanes of each row group
        #pragma unroll
        for (int r = 0; r < 4; r++) {
            float mx = fmaxf(fmaxf(s[r][0], s[r][1]), fmaxf(s[r][2], s[r][3]));
            #pragma unroll
            for (int ofs = 8; ofs; ofs >>= 1)
                mx = fmaxf(mx, __shfl_xor_sync(0xffffffffu, mx, ofs));
            float mn = fmaxf(mrow[r], mx);
            float corr = __expf(mrow[r] - mn);
            mrow[r] = mn;
            float rs = 0.0f;
            #pragma unroll
            for (int c = 0; c < 4; c++) {
                s[r][c] = __expf(s[r][c] - mn);
                rs += s[r][c];
            }
            #pragma unroll
            for (int ofs = 8; ofs; ofs >>= 1)
                rs += __shfl_xor_sync(0xffffffffu, rs, ofs);
            lrow[r] = lrow[r] * corr + rs;
            #pragma unroll
            for (int c = 0; c < 4; c++) o[r][c] *= corr;
            float4 pv = make_float4(s[r][0], s[r][1], s[r][2], s[r][3]);
            *(float4*)&Ps[(i4 + r) * DHD + j4] = pv;
        }
        __syncthreads();

        // O += P @ V
        #pragma unroll 2
        for (int k = 0; k < 64; k += 4) {
            float4 v0 = *(const float4*)&Vs[(k + 0) * DHD + j4];
            float4 v1 = *(const float4*)&Vs[(k + 1) * DHD + j4];
            float4 v2 = *(const float4*)&Vs[(k + 2) * DHD + j4];
            float4 v3 = *(const float4*)&Vs[(k + 3) * DHD + j4];
            float vf[4][4] = {{v0.x, v0.y, v0.z, v0.w},
                              {v1.x, v1.y, v1.z, v1.w},
                              {v2.x, v2.y, v2.z, v2.w},
                              {v3.x, v3.y, v3.z, v3.w}};
            #pragma unroll
            for (int r = 0; r < 4; r++) {
                float4 pq = *(const float4*)&Ps[(i4 + r) * DHD + k];
                float pf[4] = {pq.x, pq.y, pq.z, pq.w};
                #pragma unroll
                for (int kk = 0; kk < 4; kk++)
                    #pragma unroll
                    for (int c = 0; c < 4; c++)
                        o[r][c] += pf[kk] * vf[kk][c];
            }
        }
    }

    // Normalize and write context in [B, L, D] layout
    const int bb = bh / HH, hh = bh % HH;
    #pragma unroll
    for (int r = 0; r < 4; r++) {
        float inv = 1.0f / lrow[r];
        float4 ov = make_float4(o[r][0] * inv, o[r][1] * inv,
                                o[r][2] * inv, o[r][3] * inv);
        *(float4*)&g_ctx[((size_t)(bb * LQ + q0 + i4 + r)) * DD + hh * DHD + j4] = ov;
    }
}

// ---------------------------------------------------------------------------

extern "C" void kernel_launch(void* const* d_in, const int* in_sizes, int n_in,
                              void* d_out, int out_size) {
    const float* X   = (const float*)d_in[0];
    const float* Wq  = (const float*)d_in[1];
    const float* Wk  = (const float*)d_in[2];
    const float* Wv  = (const float*)d_in[3];
    const float* Wo  = (const float*)d_in[4];
    const float* bo  = (const float*)d_in[5];
    const float* Kbg = (const float*)d_in[6];
    const float* Vbg = (const float*)d_in[7];
    float* out = (float*)d_out;

    cudaFuncSetAttribute(attn_kernel, cudaFuncAttributeMaxDynamicSharedMemorySize, 65536);

    dim3 gq(DD / 128, MTOT / 128, 3);
    qkv_gemm<<<gq, 256>>>(X, Wq, Wk, Wv);

    attn_kernel<<<dim3(LQ / 64, BH), 256, 65536>>>(Kbg, Vbg);

    dim3 go(DD / 128, MTOT / 128);
    out_gemm<<<go, 256>>>(Wo, bo, out);
}

// round 8
// speedup vs baseline: 1.4842x; 1.4842x over previous
#include <cuda_runtime.h>
#include <cuda_bf16.h>
#include <cstdint>

#define BQ 4
#define LQ 1024
#define DD 1280
#define HH 20
#define DHD 64
#define BH (BQ*HH)          // 80
#define MTOT (BQ*LQ)        // 4096
#define ALPHA 0.48f
#define SCALE 0.125f        // 1/sqrt(64)

// ---------------------------------------------------------------------------
// Static device scratch (allocation-free)
// ---------------------------------------------------------------------------
__device__ float g_q[BH*LQ*DHD];
__device__ float g_k[BH*LQ*DHD];
__device__ float g_v[BH*LQ*DHD];

// bf16 two-term splits
__device__ __nv_bfloat16 g_xh[MTOT*DD],  g_xl[MTOT*DD];       // X  [m][k]
__device__ __nv_bfloat16 g_ctxh[MTOT*DD], g_ctxl[MTOT*DD];    // ctx [m][k]
__device__ __nv_bfloat16 g_wth[4*DD*DD], g_wtl[4*DD*DD];      // W^T [n][k] (q,k,v,o)

// ---------------------------------------------------------------------------
// Split helpers: x = hi + lo, both bf16
// ---------------------------------------------------------------------------
__device__ __forceinline__ void split1(float x, unsigned& h, unsigned& l) {
    __nv_bfloat16 bh = __float2bfloat16_rn(x);
    float r = x - __bfloat162float(bh);
    __nv_bfloat16 bl = __float2bfloat16_rn(r);
    h = (unsigned)(*(unsigned short*)&bh);
    l = (unsigned)(*(unsigned short*)&bl);
}
__device__ __forceinline__ void split4(float4 v, uint2& hh, uint2& ll) {
    unsigned h0,l0,h1,l1,h2,l2,h3,l3;
    split1(v.x,h0,l0); split1(v.y,h1,l1); split1(v.z,h2,l2); split1(v.w,h3,l3);
    hh.x = h0 | (h1<<16);  hh.y = h2 | (h3<<16);
    ll.x = l0 | (l1<<16);  ll.y = l2 | (l3<<16);
}

__device__ __forceinline__ uint32_t smem_u32(const void* p) {
    uint32_t a;
    asm("{ .reg .u64 t; cvta.to.shared.u64 t, %1; cvt.u32.u64 %0, t; }"
        : "=r"(a) : "l"(p));
    return a;
}

// ---------------------------------------------------------------------------
// split_x: X fp32 -> (g_xh, g_xl)
// ---------------------------------------------------------------------------
__global__ void __launch_bounds__(256) split_x(const float* __restrict__ X) {
    int i = blockIdx.x * 256 + threadIdx.x;           // float4 index
    float4 v = ((const float4*)X)[i];
    uint2 hh, ll;
    split4(v, hh, ll);
    ((uint2*)g_xh)[i] = hh;
    ((uint2*)g_xl)[i] = ll;
}

// ---------------------------------------------------------------------------
// split_wT: W [k][n] fp32 -> W^T [n][k] bf16 hi/lo  (32x32 smem transpose)
// ---------------------------------------------------------------------------
__global__ void __launch_bounds__(256) split_wT(const float* __restrict__ Wq,
                                                const float* __restrict__ Wk,
                                                const float* __restrict__ Wv,
                                                const float* __restrict__ Wo) {
    const float* W = (blockIdx.z == 0) ? Wq : (blockIdx.z == 1) ? Wk
                   : (blockIdx.z == 2) ? Wv : Wo;
    __nv_bfloat16* dh = g_wth + (size_t)blockIdx.z * DD * DD;
    __nv_bfloat16* dl = g_wtl + (size_t)blockIdx.z * DD * DD;

    __shared__ float tile[32][33];
    const int t = threadIdx.x, tx = t & 31, ty = t >> 5;
    const int k0 = blockIdx.y * 32, n0 = blockIdx.x * 32;

    #pragma unroll
    for (int r = ty; r < 32; r += 8)
        tile[r][tx] = W[(size_t)(k0 + r) * DD + n0 + tx];
    __syncthreads();
    #pragma unroll
    for (int r = ty; r < 32; r += 8) {
        float v = tile[tx][r];                 // W[k0+tx][n0+r]
        unsigned h, l;
        split1(v, h, l);
        size_t idx = (size_t)(n0 + r) * DD + k0 + tx;
        dh[idx] = *(__nv_bfloat16*)&h;
        dl[idx] = *(__nv_bfloat16*)&l;
    }
}

// ---------------------------------------------------------------------------
// mma.sync bf16 GEMM core.  Block tile 128x128, K-chunk 32, 8 warps (2m x 4n),
// warp tile 64x32 -> 4 m-frags (m16) x 4 n-frags (n8), k16 per mma.
// 3-term split: AhBh + AhBl + AlBh.
// smem row stride 80 B (40 bf16) -> conflict-free ldmatrix.
// ---------------------------------------------------------------------------
#define KC2 32
#define ROWB 80
#define SA_H 0
#define SA_L 10240
#define SB_H 20480
#define SB_L 30720
#define SM_GEMM 40960

__device__ __forceinline__ void ldmx4(uint32_t addr, uint32_t* r) {
    asm volatile("ldmatrix.sync.aligned.m8n8.x4.shared.b16 {%0,%1,%2,%3}, [%4];"
                 : "=r"(r[0]), "=r"(r[1]), "=r"(r[2]), "=r"(r[3]) : "r"(addr));
}
__device__ __forceinline__ void ldmx2(uint32_t addr, uint32_t* r) {
    asm volatile("ldmatrix.sync.aligned.m8n8.x2.shared.b16 {%0,%1}, [%2];"
                 : "=r"(r[0]), "=r"(r[1]) : "r"(addr));
}
__device__ __forceinline__ void mma16816(float* c, const uint32_t* a, const uint32_t* b) {
    asm volatile(
        "mma.sync.aligned.m16n8k16.row.col.f32.bf16.bf16.f32 "
        "{%0,%1,%2,%3}, {%4,%5,%6,%7}, {%8,%9}, {%0,%1,%2,%3};"
        : "+f"(c[0]), "+f"(c[1]), "+f"(c[2]), "+f"(c[3])
        : "r"(a[0]), "r"(a[1]), "r"(a[2]), "r"(a[3]), "r"(b[0]), "r"(b[1]));
}

// Runs the mainloop; leaves acc[mf][nf][4] per thread.
__device__ __forceinline__ void mma_mainloop(const __nv_bfloat16* __restrict__ Ah,
                                             const __nv_bfloat16* __restrict__ Al,
                                             const __nv_bfloat16* __restrict__ Bh,
                                             const __nv_bfloat16* __restrict__ Bl,
                                             char* sm, int bm, int bn,
                                             float acc[4][4][4]) {
    const int t = threadIdx.x;
    const int wid = t >> 5, lane = t & 31;
    const int wm = (wid >> 2) * 64, wn = (wid & 3) * 32;
    const uint32_t smb = smem_u32(sm);

    // ldmatrix lane address components
    const int a_r  = lane & 15;
    const int a_k8 = (lane >> 4) * 16;        // byte offset (+8 bf16)
    const int b_r  = lane & 7;
    const int b_k8 = ((lane >> 3) & 1) * 16;

    for (int c = 0; c < DD / KC2; c++) {
        const int k0 = c * KC2;
        __syncthreads();
        // ---- load A tiles (128 x 32 bf16, hi+lo): 1024 uint4 total
        #pragma unroll
        for (int i = 0; i < 4; i++) {
            int id = t + i * 256;             // 0..1023
            int sel = id >> 9;                // 0: hi, 1: lo
            int idx = id & 511;
            int row = idx >> 2, q = idx & 3;
            const __nv_bfloat16* src = (sel ? Al : Ah) + (size_t)(bm + row) * DD + k0 + q * 8;
            uint4 v = *(const uint4*)src;
            *(uint4*)(sm + (sel ? SA_L : SA_H) + row * ROWB + q * 16) = v;
        }
        // ---- load B tiles (W^T rows: [n][k])
        #pragma unroll
        for (int i = 0; i < 4; i++) {
            int id = t + i * 256;
            int sel = id >> 9;
            int idx = id & 511;
            int row = idx >> 2, q = idx & 3;
            const __nv_bfloat16* src = (sel ? Bl : Bh) + (size_t)(bn + row) * DD + k0 + q * 8;
            uint4 v = *(const uint4*)src;
            *(uint4*)(sm + (sel ? SB_L : SB_H) + row * ROWB + q * 16) = v;
        }
        __syncthreads();

        #pragma unroll
        for (int ks = 0; ks < KC2; ks += 16) {
            uint32_t ah[4][4], al[4][4], bh[4][2], bl[4][2];
            #pragma unroll
            for (int mf = 0; mf < 4; mf++) {
                uint32_t ra = (wm + mf * 16 + a_r) * ROWB + ks * 2 + a_k8;
                ldmx4(smb + SA_H + ra, ah[mf]);
                ldmx4(smb + SA_L + ra, al[mf]);
            }
            #pragma unroll
            for (int nf = 0; nf < 4; nf++) {
                uint32_t rb = (wn + nf * 8 + b_r) * ROWB + ks * 2 + b_k8;
                ldmx2(smb + SB_H + rb, bh[nf]);
                ldmx2(smb + SB_L + rb, bl[nf]);
            }
            #pragma unroll
            for (int mf = 0; mf < 4; mf++)
                #pragma unroll
                for (int nf = 0; nf < 4; nf++) {
                    mma16816(acc[mf][nf], ah[mf], bh[nf]);
                    mma16816(acc[mf][nf], ah[mf], bl[nf]);
                    mma16816(acc[mf][nf], al[mf], bh[nf]);
                }
        }
    }
}

// QKV GEMM: writes scattered into [B*H, L, DH] fp32
__global__ void __launch_bounds__(256) mma_qkv() {
    __shared__ char sm[SM_GEMM];
    const int t = threadIdx.x, wid = t >> 5, lane = t & 31;
    const int wm = (wid >> 2) * 64, wn = (wid & 3) * 32;
    const int bm = blockIdx.y * 128, bn = blockIdx.x * 128;
    const int z = blockIdx.z;

    const __nv_bfloat16* Bh = g_wth + (size_t)z * DD * DD;
    const __nv_bfloat16* Bl = g_wtl + (size_t)z * DD * DD;
    float* dst = (z == 0) ? g_q : (z == 1) ? g_k : g_v;

    float acc[4][4][4] = {};
    mma_mainloop(g_xh, g_xl, Bh, Bl, sm, bm, bn, acc);

    const int gid = lane >> 2, tig = lane & 3;
    #pragma unroll
    for (int mf = 0; mf < 4; mf++) {
        #pragma unroll
        for (int nf = 0; nf < 4; nf++) {
            int m = bm + wm + mf * 16 + gid;
            int n = bn + wn + nf * 8 + tig * 2;
            int hh = n >> 6, dh = n & 63;
            {
                int bb = m >> 10, lq2 = m & 1023;
                float* p = dst + (((size_t)bb * HH + hh) * LQ + lq2) * DHD + dh;
                *(float2*)p = make_float2(acc[mf][nf][0], acc[mf][nf][1]);
            }
            {
                int m2 = m + 8;
                int bb = m2 >> 10, lq2 = m2 & 1023;
                float* p = dst + (((size_t)bb * HH + hh) * LQ + lq2) * DHD + dh;
                *(float2*)p = make_float2(acc[mf][nf][2], acc[mf][nf][3]);
            }
        }
    }
}

// Output GEMM: ctx (bf16 split) @ Wo^T + bias -> out
__global__ void __launch_bounds__(256) mma_out(const float* __restrict__ bo,
                                               float* __restrict__ out) {
    __shared__ char sm[SM_GEMM];
    const int t = threadIdx.x, wid = t >> 5, lane = t & 31;
    const int wm = (wid >> 2) * 64, wn = (wid & 3) * 32;
    const int bm = blockIdx.y * 128, bn = blockIdx.x * 128;

    const __nv_bfloat16* Bh = g_wth + (size_t)3 * DD * DD;
    const __nv_bfloat16* Bl = g_wtl + (size_t)3 * DD * DD;

    float acc[4][4][4] = {};
    mma_mainloop(g_ctxh, g_ctxl, Bh, Bl, sm, bm, bn, acc);

    const int gid = lane >> 2, tig = lane & 3;
    #pragma unroll
    for (int mf = 0; mf < 4; mf++) {
        #pragma unroll
        for (int nf = 0; nf < 4; nf++) {
            int m = bm + wm + mf * 16 + gid;
            int n = bn + wn + nf * 8 + tig * 2;
            float2 bv = *(const float2*)(bo + n);
            *(float2*)(out + (size_t)m * DD + n) =
                make_float2(acc[mf][nf][0] + bv.x, acc[mf][nf][1] + bv.y);
            *(float2*)(out + (size_t)(m + 8) * DD + n) =
                make_float2(acc[mf][nf][2] + bv.x, acc[mf][nf][3] + bv.y);
        }
    }
}

// ---------------------------------------------------------------------------
// Flash attention (unchanged math); epilogue writes ctx as bf16 hi/lo split.
// ---------------------------------------------------------------------------
__device__ __forceinline__ void stsw(char* buf, int dh, int l, float v) {
    int off = (dh << 8) + (l << 2);
    off ^= ((off >> 10) & 7) << 4;
    *(float*)(buf + off) = v;
}
__device__ __forceinline__ float4 ldsw(const char* buf, int dh, int col4) {
    int off = (dh << 8) + (col4 << 2);
    off ^= ((off >> 10) & 7) << 4;
    return *(const float4*)(buf + off);
}

__global__ void __launch_bounds__(256) attn_kernel(const float* __restrict__ Kbg,
                                                   const float* __restrict__ Vbg) {
    extern __shared__ char smbase[];
    char*  Qb = smbase;
    char*  Kb = smbase + 16384;
    float* Vs = (float*)(smbase + 32768);
    float* Ps = (float*)(smbase + 49152);

    const int t  = threadIdx.x;
    const int i4 = (t >> 4) << 2;
    const int j4 = (t & 15) << 2;
    const int bh = blockIdx.y;
    const int q0 = blockIdx.x << 6;

    {
        const float* Qg = g_q + ((size_t)bh * LQ + q0) * DHD;
        #pragma unroll
        for (int it = 0; it < 4; it++) {
            int fidx = t + (it << 8);
            int l = fidx >> 4;
            int dh4 = (fidx & 15) << 2;
            float4 v = *(const float4*)(Qg + l * DHD + dh4);
            stsw(Qb, dh4 + 0, l, v.x);
            stsw(Qb, dh4 + 1, l, v.y);
            stsw(Qb, dh4 + 2, l, v.z);
            stsw(Qb, dh4 + 3, l, v.w);
        }
    }

    float o[4][4] = {};
    float mrow[4] = {-1e30f, -1e30f, -1e30f, -1e30f};
    float lrow[4] = {};

    for (int tile = 0; tile < 32; tile++) {
        __syncthreads();
        const int kv0 = tile << 6;
        const float *Ksrc, *Vsrc;
        float mult;
        if (kv0 < LQ) {
            Ksrc = g_k + ((size_t)bh * LQ + kv0) * DHD;
            Vsrc = g_v + ((size_t)bh * LQ + kv0) * DHD;
            mult = 1.0f;
        } else {
            Ksrc = Kbg + ((size_t)bh * LQ + (kv0 - LQ)) * DHD;
            Vsrc = Vbg + ((size_t)bh * LQ + (kv0 - LQ)) * DHD;
            mult = ALPHA;
        }
        #pragma unroll
        for (int it = 0; it < 4; it++) {
            int fidx = t + (it << 8);
            int l = fidx >> 4;
            int dh4 = (fidx & 15) << 2;
            float4 kv = *(const float4*)(Ksrc + l * DHD + dh4);
            stsw(Kb, dh4 + 0, l, kv.x * mult);
            stsw(Kb, dh4 + 1, l, kv.y * mult);
            stsw(Kb, dh4 + 2, l, kv.z * mult);
            stsw(Kb, dh4 + 3, l, kv.w * mult);
            float4 vv = *(const float4*)(Vsrc + l * DHD + dh4);
            vv.x *= mult; vv.y *= mult; vv.z *= mult; vv.w *= mult;
            *(float4*)&Vs[l * DHD + dh4] = vv;
        }
        __syncthreads();

        float s[4][4] = {};
        #pragma unroll 8
        for (int k = 0; k < 64; k++) {
            float4 qv = ldsw(Qb, k, i4);
            float4 kq = ldsw(Kb, k, j4);
            float qf[4] = {qv.x, qv.y, qv.z, qv.w};
            float kf[4] = {kq.x, kq.y, kq.z, kq.w};
            #pragma unroll
            for (int r = 0; r < 4; r++)
                #pragma unroll
                for (int c = 0; c < 4; c++)
                    s[r][c] += qf[r] * kf[c];
        }
        #pragma unroll
        for (int r = 0; r < 4; r++)
            #pragma unroll
            for (int c = 0; c < 4; c++)
                s[r][c] *= SCALE;

        #pragma unroll
        for (int r = 0; r < 4; r++) {
            float mx = fmaxf(fmaxf(s[r][0], s[r][1]), fmaxf(s[r][2], s[r][3]));
            #pragma unroll
            for (int ofs = 8; ofs; ofs >>= 1)
                mx = fmaxf(mx, __shfl_xor_sync(0xffffffffu, mx, ofs));
            float mn = fmaxf(mrow[r], mx);
            float corr = __expf(mrow[r] - mn);
            mrow[r] = mn;
            float rs = 0.0f;
            #pragma unroll
            for (int c = 0; c < 4; c++) {
                s[r][c] = __expf(s[r][c] - mn);
                rs += s[r][c];
            }
            #pragma unroll
            for (int ofs = 8; ofs; ofs >>= 1)
                rs += __shfl_xor_sync(0xffffffffu, rs, ofs);
            lrow[r] = lrow[r] * corr + rs;
            #pragma unroll
            for (int c = 0; c < 4; c++) o[r][c] *= corr;
            float4 pv = make_float4(s[r][0], s[r][1], s[r][2], s[r][3]);
            *(float4*)&Ps[(i4 + r) * DHD + j4] = pv;
        }
        __syncthreads();

        #pragma unroll 2
        for (int k = 0; k < 64; k += 4) {
            float4 v0 = *(const float4*)&Vs[(k + 0) * DHD + j4];
            float4 v1 = *(const float4*)&Vs[(k + 1) * DHD + j4];
            float4 v2 = *(const float4*)&Vs[(k + 2) * DHD + j4];
            float4 v3 = *(const float4*)&Vs[(k + 3) * DHD + j4];
            float vf[4][4] = {{v0.x, v0.y, v0.z, v0.w},
                              {v1.x, v1.y, v1.z, v1.w},
                              {v2.x, v2.y, v2.z, v2.w},
                              {v3.x, v3.y, v3.z, v3.w}};
            #pragma unroll
            for (int r = 0; r < 4; r++) {
                float4 pq = *(const float4*)&Ps[(i4 + r) * DHD + k];
                float pf[4] = {pq.x, pq.y, pq.z, pq.w};
                #pragma unroll
                for (int kk = 0; kk < 4; kk++)
                    #pragma unroll
                    for (int c = 0; c < 4; c++)
                        o[r][c] += pf[kk] * vf[kk][c];
            }
        }
    }

    // Epilogue: normalize and write ctx as bf16 hi/lo split in [B, L, D] layout
    const int bb = bh / HH, hh = bh % HH;
    #pragma unroll
    for (int r = 0; r < 4; r++) {
        float inv = 1.0f / lrow[r];
        float4 ov = make_float4(o[r][0] * inv, o[r][1] * inv,
                                o[r][2] * inv, o[r][3] * inv);
        uint2 hv, lv;
        split4(ov, hv, lv);
        size_t base = ((size_t)(bb * LQ + q0 + i4 + r)) * DD + hh * DHD + j4;
        *(uint2*)&g_ctxh[base] = hv;
        *(uint2*)&g_ctxl[base] = lv;
    }
}

// ---------------------------------------------------------------------------

extern "C" void kernel_launch(void* const* d_in, const int* in_sizes, int n_in,
                              void* d_out, int out_size) {
    const float* X   = (const float*)d_in[0];
    const float* Wq  = (const float*)d_in[1];
    const float* Wk  = (const float*)d_in[2];
    const float* Wv  = (const float*)d_in[3];
    const float* Wo  = (const float*)d_in[4];
    const float* bo  = (const float*)d_in[5];
    const float* Kbg = (const float*)d_in[6];
    const float* Vbg = (const float*)d_in[7];
    float* out = (float*)d_out;

    cudaFuncSetAttribute(attn_kernel, cudaFuncAttributeMaxDynamicSharedMemorySize, 65536);

    split_x<<<MTOT * DD / 4 / 256, 256>>>(X);
    split_wT<<<dim3(DD / 32, DD / 32, 4), 256>>>(Wq, Wk, Wv, Wo);

    mma_qkv<<<dim3(DD / 128, MTOT / 128, 3), 256>>>();

    attn_kernel<<<dim3(LQ / 64, BH), 256, 65536>>>(Kbg, Vbg);

    mma_out<<<dim3(DD / 128, MTOT / 128), 256>>>(bo, out);
}

// round 9
// speedup vs baseline: 2.3768x; 1.6014x over previous
#include <cuda_runtime.h>
#include <cuda_bf16.h>
#include <cstdint>

#define BQ 4
#define LQ 1024
#define DD 1280
#define HH 20
#define DHD 64
#define BH (BQ*HH)          // 80
#define MTOT (BQ*LQ)        // 4096
#define KV2 2048
#define ALPHA 0.48f
#define SCALE 0.125f        // 1/sqrt(64)

// ---------------------------------------------------------------------------
// Static device scratch (allocation-free)
// ---------------------------------------------------------------------------
// bf16 two-term splits
__device__ __nv_bfloat16 g_xh[MTOT*DD],  g_xl[MTOT*DD];        // X  [m][k]
__device__ __nv_bfloat16 g_ctxh[MTOT*DD], g_ctxl[MTOT*DD];     // ctx [m][k]
__device__ __nv_bfloat16 g_wth[4*DD*DD], g_wtl[4*DD*DD];       // W^T [n][k]
__device__ __nv_bfloat16 g_qh[BH*LQ*DHD],  g_ql[BH*LQ*DHD];    // Q*SCALE split
__device__ __nv_bfloat16 g_kh[BH*KV2*DHD], g_kl[BH*KV2*DHD];   // K (self+bg)
__device__ __nv_bfloat16 g_vh[BH*KV2*DHD], g_vl[BH*KV2*DHD];   // V (self+bg)

// ---------------------------------------------------------------------------
// Split helpers: x = hi + lo, both bf16
// ---------------------------------------------------------------------------
__device__ __forceinline__ void split1(float x, unsigned& h, unsigned& l) {
    __nv_bfloat16 bh = __float2bfloat16_rn(x);
    float r = x - __bfloat162float(bh);
    __nv_bfloat16 bl = __float2bfloat16_rn(r);
    h = (unsigned)(*(unsigned short*)&bh);
    l = (unsigned)(*(unsigned short*)&bl);
}
__device__ __forceinline__ void split4(float4 v, uint2& hh, uint2& ll) {
    unsigned h0,l0,h1,l1,h2,l2,h3,l3;
    split1(v.x,h0,l0); split1(v.y,h1,l1); split1(v.z,h2,l2); split1(v.w,h3,l3);
    hh.x = h0 | (h1<<16);  hh.y = h2 | (h3<<16);
    ll.x = l0 | (l1<<16);  ll.y = l2 | (l3<<16);
}
// pack two floats into bf16x2 hi-word / lo-word pair (residual split)
__device__ __forceinline__ void psplit2(float x, float y, uint32_t& h, uint32_t& l) {
    unsigned hx,lx,hy,ly;
    split1(x,hx,lx); split1(y,hy,ly);
    h = hx | (hy << 16);
    l = lx | (ly << 16);
}

__device__ __forceinline__ uint32_t smem_u32(const void* p) {
    uint32_t a;
    asm("{ .reg .u64 t; cvta.to.shared.u64 t, %1; cvt.u32.u64 %0, t; }"
        : "=r"(a) : "l"(p));
    return a;
}

// ---------------------------------------------------------------------------
// split_x: X fp32 -> (g_xh, g_xl)
// ---------------------------------------------------------------------------
__global__ void __launch_bounds__(256) split_x(const float* __restrict__ X) {
    int i = blockIdx.x * 256 + threadIdx.x;           // float4 index
    float4 v = ((const float4*)X)[i];
    uint2 hh, ll;
    split4(v, hh, ll);
    ((uint2*)g_xh)[i] = hh;
    ((uint2*)g_xl)[i] = ll;
}

// ---------------------------------------------------------------------------
// split_bg: alpha * {Kbg,Vbg} fp32 -> bf16 splits at kv slots [1024, 2048)
// ---------------------------------------------------------------------------
__global__ void __launch_bounds__(256) split_bg(const float* __restrict__ Kbg,
                                                const float* __restrict__ Vbg) {
    const int z = blockIdx.y;
    const float* src = z ? Vbg : Kbg;
    __nv_bfloat16* dsth = z ? g_vh : g_kh;
    __nv_bfloat16* dstl = z ? g_vl : g_kl;
    size_t i = (size_t)blockIdx.x * 256 + threadIdx.x;  // float4 idx, BH*1024*64/4
    float4 v = ((const float4*)src)[i];
    v.x *= ALPHA; v.y *= ALPHA; v.z *= ALPHA; v.w *= ALPHA;
    uint2 hh, ll;
    split4(v, hh, ll);
    size_t e = i * 4;
    size_t bh = e >> 16;            // / (1024*64)
    size_t rem = e & 65535;
    size_t d = (bh << 17) + 65536 + rem;
    *(uint2*)&dsth[d] = hh;
    *(uint2*)&dstl[d] = ll;
}

// ---------------------------------------------------------------------------
// split_wT: W [k][n] fp32 -> W^T [n][k] bf16 hi/lo  (32x32 smem transpose)
// ---------------------------------------------------------------------------
__global__ void __launch_bounds__(256) split_wT(const float* __restrict__ Wq,
                                                const float* __restrict__ Wk,
                                                const float* __restrict__ Wv,
                                                const float* __restrict__ Wo) {
    const float* W = (blockIdx.z == 0) ? Wq : (blockIdx.z == 1) ? Wk
                   : (blockIdx.z == 2) ? Wv : Wo;
    __nv_bfloat16* dh = g_wth + (size_t)blockIdx.z * DD * DD;
    __nv_bfloat16* dl = g_wtl + (size_t)blockIdx.z * DD * DD;

    __shared__ float tile[32][33];
    const int t = threadIdx.x, tx = t & 31, ty = t >> 5;
    const int k0 = blockIdx.y * 32, n0 = blockIdx.x * 32;

    #pragma unroll
    for (int r = ty; r < 32; r += 8)
        tile[r][tx] = W[(size_t)(k0 + r) * DD + n0 + tx];
    __syncthreads();
    #pragma unroll
    for (int r = ty; r < 32; r += 8) {
        float v = tile[tx][r];
        unsigned h, l;
        split1(v, h, l);
        size_t idx = (size_t)(n0 + r) * DD + k0 + tx;
        dh[idx] = *(__nv_bfloat16*)&h;
        dl[idx] = *(__nv_bfloat16*)&l;
    }
}

// ---------------------------------------------------------------------------
// mma.sync primitives
// ---------------------------------------------------------------------------
__device__ __forceinline__ void ldmx4(uint32_t addr, uint32_t* r) {
    asm volatile("ldmatrix.sync.aligned.m8n8.x4.shared.b16 {%0,%1,%2,%3}, [%4];"
                 : "=r"(r[0]), "=r"(r[1]), "=r"(r[2]), "=r"(r[3]) : "r"(addr));
}
__device__ __forceinline__ void ldmx2(uint32_t addr, uint32_t* r) {
    asm volatile("ldmatrix.sync.aligned.m8n8.x2.shared.b16 {%0,%1}, [%2];"
                 : "=r"(r[0]), "=r"(r[1]) : "r"(addr));
}
__device__ __forceinline__ void ldmx2t(uint32_t addr, uint32_t* r) {
    asm volatile("ldmatrix.sync.aligned.m8n8.x2.trans.shared.b16 {%0,%1}, [%2];"
                 : "=r"(r[0]), "=r"(r[1]) : "r"(addr));
}
__device__ __forceinline__ void mma16816(float* c, const uint32_t* a, const uint32_t* b) {
    asm volatile(
        "mma.sync.aligned.m16n8k16.row.col.f32.bf16.bf16.f32 "
        "{%0,%1,%2,%3}, {%4,%5,%6,%7}, {%8,%9}, {%0,%1,%2,%3};"
        : "+f"(c[0]), "+f"(c[1]), "+f"(c[2]), "+f"(c[3])
        : "r"(a[0]), "r"(a[1]), "r"(a[2]), "r"(a[3]), "r"(b[0]), "r"(b[1]));
}

// ---------------------------------------------------------------------------
// GEMM core.  Block tile 128x128, K-chunk 32, 8 warps (2m x 4n), warp 64x32.
// 3-term split: AhBh + AhBl + AlBh.  smem row stride 80 B.
// ---------------------------------------------------------------------------
#define KC2 32
#define ROWB 80
#define SA_H 0
#define SA_L 10240
#define SB_H 20480
#define SB_L 30720
#define SM_GEMM 40960

__device__ __forceinline__ void mma_mainloop(const __nv_bfloat16* __restrict__ Ah,
                                             const __nv_bfloat16* __restrict__ Al,
                                             const __nv_bfloat16* __restrict__ Bh,
                                             const __nv_bfloat16* __restrict__ Bl,
                                             char* sm, int bm, int bn,
                                             float acc[4][4][4]) {
    const int t = threadIdx.x;
    const int wid = t >> 5, lane = t & 31;
    const int wm = (wid >> 2) * 64, wn = (wid & 3) * 32;
    const uint32_t smb = smem_u32(sm);

    const int a_r  = lane & 15;
    const int a_k8 = (lane >> 4) * 16;
    const int b_r  = lane & 7;
    const int b_k8 = ((lane >> 3) & 1) * 16;

    for (int c = 0; c < DD / KC2; c++) {
        const int k0 = c * KC2;
        __syncthreads();
        #pragma unroll
        for (int i = 0; i < 4; i++) {
            int id = t + i * 256;
            int sel = id >> 9;
            int idx = id & 511;
            int row = idx >> 2, q = idx & 3;
            const __nv_bfloat16* src = (sel ? Al : Ah) + (size_t)(bm + row) * DD + k0 + q * 8;
            uint4 v = *(const uint4*)src;
            *(uint4*)(sm + (sel ? SA_L : SA_H) + row * ROWB + q * 16) = v;
        }
        #pragma unroll
        for (int i = 0; i < 4; i++) {
            int id = t + i * 256;
            int sel = id >> 9;
            int idx = id & 511;
            int row = idx >> 2, q = idx & 3;
            const __nv_bfloat16* src = (sel ? Bl : Bh) + (size_t)(bn + row) * DD + k0 + q * 8;
            uint4 v = *(const uint4*)src;
            *(uint4*)(sm + (sel ? SB_L : SB_H) + row * ROWB + q * 16) = v;
        }
        __syncthreads();

        #pragma unroll
        for (int ks = 0; ks < KC2; ks += 16) {
            uint32_t ah[4][4], al[4][4], bh[4][2], bl[4][2];
            #pragma unroll
            for (int mf = 0; mf < 4; mf++) {
                uint32_t ra = (wm + mf * 16 + a_r) * ROWB + ks * 2 + a_k8;
                ldmx4(smb + SA_H + ra, ah[mf]);
                ldmx4(smb + SA_L + ra, al[mf]);
            }
            #pragma unroll
            for (int nf = 0; nf < 4; nf++) {
                uint32_t rb = (wn + nf * 8 + b_r) * ROWB + ks * 2 + b_k8;
                ldmx2(smb + SB_H + rb, bh[nf]);
                ldmx2(smb + SB_L + rb, bl[nf]);
            }
            #pragma unroll
            for (int mf = 0; mf < 4; mf++)
                #pragma unroll
                for (int nf = 0; nf < 4; nf++) {
                    mma16816(acc[mf][nf], ah[mf], bh[nf]);
                    mma16816(acc[mf][nf], ah[mf], bl[nf]);
                    mma16816(acc[mf][nf], al[mf], bh[nf]);
                }
        }
    }
}

// QKV GEMM: epilogue splits directly to bf16 hi/lo in attention layout.
__global__ void __launch_bounds__(256) mma_qkv() {
    __shared__ char sm[SM_GEMM];
    const int t = threadIdx.x, wid = t >> 5, lane = t & 31;
    const int wm = (wid >> 2) * 64, wn = (wid & 3) * 32;
    const int bm = blockIdx.y * 128, bn = blockIdx.x * 128;
    const int z = blockIdx.z;

    const __nv_bfloat16* Bh = g_wth + (size_t)z * DD * DD;
    const __nv_bfloat16* Bl = g_wtl + (size_t)z * DD * DD;
    __nv_bfloat16* dh_ = (z == 0) ? g_qh : (z == 1) ? g_kh : g_vh;
    __nv_bfloat16* dl_ = (z == 0) ? g_ql : (z == 1) ? g_kl : g_vl;
    const float mul = (z == 0) ? SCALE : 1.0f;
    const int shift = (z == 0) ? 16 : 17;    // per-bh element stride (LQ|KV2)*64

    float acc[4][4][4] = {};
    mma_mainloop(g_xh, g_xl, Bh, Bl, sm, bm, bn, acc);

    const int gid = lane >> 2, tig = lane & 3;
    #pragma unroll
    for (int mf = 0; mf < 4; mf++) {
        #pragma unroll
        for (int nf = 0; nf < 4; nf++) {
            int n = bn + wn + nf * 8 + tig * 2;
            int hh = n >> 6, dh = n & 63;
            #pragma unroll
            for (int half = 0; half < 2; half++) {
                int m = bm + wm + mf * 16 + gid + half * 8;
                int bb = m >> 10, lq2 = m & 1023;
                int bhh = bb * HH + hh;
                size_t idx = ((size_t)bhh << shift) + ((size_t)lq2 << 6) + dh;
                uint32_t hv, lv;
                psplit2(acc[mf][nf][half*2] * mul, acc[mf][nf][half*2+1] * mul, hv, lv);
                *(uint32_t*)&dh_[idx] = hv;
                *(uint32_t*)&dl_[idx] = lv;
            }
        }
    }
}

// Output GEMM: ctx (bf16 split) @ Wo^T + bias -> out
__global__ void __launch_bounds__(256) mma_out(const float* __restrict__ bo,
                                               float* __restrict__ out) {
    __shared__ char sm[SM_GEMM];
    const int t = threadIdx.x, wid = t >> 5, lane = t & 31;
    const int wm = (wid >> 2) * 64, wn = (wid & 3) * 32;
    const int bm = blockIdx.y * 128, bn = blockIdx.x * 128;

    const __nv_bfloat16* Bh = g_wth + (size_t)3 * DD * DD;
    const __nv_bfloat16* Bl = g_wtl + (size_t)3 * DD * DD;

    float acc[4][4][4] = {};
    mma_mainloop(g_ctxh, g_ctxl, Bh, Bl, sm, bm, bn, acc);

    const int gid = lane >> 2, tig = lane & 3;
    #pragma unroll
    for (int mf = 0; mf < 4; mf++) {
        #pragma unroll
        for (int nf = 0; nf < 4; nf++) {
            int m = bm + wm + mf * 16 + gid;
            int n = bn + wn + nf * 8 + tig * 2;
            float2 bv = *(const float2*)(bo + n);
            *(float2*)(out + (size_t)m * DD + n) =
                make_float2(acc[mf][nf][0] + bv.x, acc[mf][nf][1] + bv.y);
            *(float2*)(out + (size_t)(m + 8) * DD + n) =
                make_float2(acc[mf][nf][2] + bv.x, acc[mf][nf][3] + bv.y);
        }
    }
}

// ---------------------------------------------------------------------------
// Tensor-core flash attention.
// Block = 128 threads (4 warps), 64 q rows per block, warp tile m16 x kv64.
// 32 kv tiles of 64.  S = (Q*SCALE) K^T via 3-term split; softmax online in
// MMA accumulators; P@V via 3-term split with register-local P fragments.
// smem row stride 144 B -> conflict-free ldmatrix.
// ---------------------------------------------------------------------------
#define SKB 144
#define AQH 0
#define AQL 9216
#define AKH 18432
#define AVH 36864
#define SM_ATTN 55296

__global__ void __launch_bounds__(128) attn_mma() {
    extern __shared__ char sm[];
    const uint32_t smb = smem_u32(sm);
    const int t = threadIdx.x, wid = t >> 5, lane = t & 31;
    const int gid = lane >> 2, tig = lane & 3;
    const int bh = blockIdx.y, q0 = blockIdx.x << 6;
    const int bb = bh / HH, hh = bh % HH;

    // ---- load Q tile (64 rows x 64 bf16, hi+lo)
    {
        const __nv_bfloat16* qh = g_qh + ((size_t)bh << 16) + ((size_t)q0 << 6);
        const __nv_bfloat16* ql = g_ql + ((size_t)bh << 16) + ((size_t)q0 << 6);
        #pragma unroll
        for (int i = 0; i < 8; i++) {
            int id = t + i * 128;            // 0..1023
            int sel = id >> 9;
            int idx = id & 511;
            int row = idx >> 3, q = idx & 7;
            const __nv_bfloat16* src = (sel ? ql : qh) + row * 64 + q * 8;
            uint4 v = *(const uint4*)src;
            *(uint4*)(sm + (sel ? AQL : AQH) + row * SKB + q * 16) = v;
        }
    }

    float oacc[8][4] = {};
    float mrow[2] = {-1e30f, -1e30f};
    float lrow[2] = {0.0f, 0.0f};

    const int a_r  = lane & 15;
    const int a_k16 = (lane >> 4) * 16;
    const int b_r  = lane & 7;
    const int b_k16 = ((lane >> 3) & 1) * 16;
    const int v_r  = (lane & 7) + ((lane >> 3) & 1) * 8;

    const uint32_t qb_h = smb + AQH + (wid * 16 + a_r) * SKB + a_k16;
    const uint32_t qb_l = smb + AQL + (wid * 16 + a_r) * SKB + a_k16;

    const size_t kvbase = (size_t)bh << 17;   // bh * 2048 * 64

    for (int tile = 0; tile < 32; tile++) {
        __syncthreads();
        // ---- load K,V tiles (hi+lo): 4 x (64 rows x 128 B)
        {
            const size_t src0 = kvbase + ((size_t)(tile << 6) << 6);
            #pragma unroll
            for (int i = 0; i < 16; i++) {
                int id = t + i * 128;        // 0..2047
                int arr = id >> 9;           // 0:Kh 1:Kl 2:Vh 3:Vl
                int idx = id & 511;
                int row = idx >> 3, q = idx & 7;
                const __nv_bfloat16* s =
                    ((arr == 0) ? g_kh : (arr == 1) ? g_kl : (arr == 2) ? g_vh : g_vl)
                    + src0 + row * 64 + q * 8;
                uint4 v = *(const uint4*)s;
                *(uint4*)(sm + AKH + arr * 9216 + row * SKB + q * 16) = v;
            }
        }
        __syncthreads();

        // ---- S = Q K^T
        float sacc[8][4] = {};
        #pragma unroll
        for (int ks = 0; ks < 4; ks++) {
            uint32_t ah[4], al[4];
            ldmx4(qb_h + ks * 32, ah);
            ldmx4(qb_l + ks * 32, al);
            #pragma unroll
            for (int nf = 0; nf < 8; nf++) {
                uint32_t kh2[2], kl2[2];
                uint32_t rb = smb + AKH + (nf * 8 + b_r) * SKB + ks * 32 + b_k16;
                ldmx2(rb, kh2);
                ldmx2(rb + 9216, kl2);
                mma16816(sacc[nf], ah, kh2);
                mma16816(sacc[nf], ah, kl2);
                mma16816(sacc[nf], al, kh2);
            }
        }

        // ---- online softmax (rows gid, gid+8)
        #pragma unroll
        for (int rr = 0; rr < 2; rr++) {
            const int o0 = rr * 2;
            float mx = -1e30f;
            #pragma unroll
            for (int nf = 0; nf < 8; nf++)
                mx = fmaxf(mx, fmaxf(sacc[nf][o0], sacc[nf][o0 + 1]));
            mx = fmaxf(mx, __shfl_xor_sync(0xffffffffu, mx, 1));
            mx = fmaxf(mx, __shfl_xor_sync(0xffffffffu, mx, 2));
            float mn = fmaxf(mrow[rr], mx);
            float corr = __expf(mrow[rr] - mn);
            mrow[rr] = mn;
            float rs = 0.0f;
            #pragma unroll
            for (int nf = 0; nf < 8; nf++) {
                float p0 = __expf(sacc[nf][o0] - mn);
                float p1 = __expf(sacc[nf][o0 + 1] - mn);
                sacc[nf][o0] = p0; sacc[nf][o0 + 1] = p1;
                rs += p0 + p1;
            }
            rs += __shfl_xor_sync(0xffffffffu, rs, 1);
            rs += __shfl_xor_sync(0xffffffffu, rs, 2);
            lrow[rr] = lrow[rr] * corr + rs;
            #pragma unroll
            for (int nf = 0; nf < 8; nf++) {
                oacc[nf][o0]     *= corr;
                oacc[nf][o0 + 1] *= corr;
            }
        }

        // ---- O += P V   (P fragments built register-locally from sacc)
        #pragma unroll
        for (int ks = 0; ks < 4; ks++) {
            const float* f0 = sacc[2 * ks];
            const float* f1 = sacc[2 * ks + 1];
            uint32_t ph[4], pl[4];
            psplit2(f0[0], f0[1], ph[0], pl[0]);
            psplit2(f0[2], f0[3], ph[1], pl[1]);
            psplit2(f1[0], f1[1], ph[2], pl[2]);
            psplit2(f1[2], f1[3], ph[3], pl[3]);
            #pragma unroll
            for (int nf = 0; nf < 8; nf++) {
                uint32_t vh2[2], vl2[2];
                uint32_t rv = smb + AVH + (ks * 16 + v_r) * SKB + nf * 16;
                ldmx2t(rv, vh2);
                ldmx2t(rv + 9216, vl2);
                mma16816(oacc[nf], ph, vh2);
                mma16816(oacc[nf], ph, vl2);
                mma16816(oacc[nf], pl, vh2);
            }
        }
    }

    // ---- epilogue: normalize, split, write ctx [B, L, D]
    const float inv0 = 1.0f / lrow[0];
    const float inv1 = 1.0f / lrow[1];
    const int lq0 = q0 + wid * 16 + gid;
    const size_t base0 = ((size_t)(bb * LQ + lq0)) * DD + hh * 64;
    const size_t base1 = ((size_t)(bb * LQ + lq0 + 8)) * DD + hh * 64;
    #pragma unroll
    for (int nf = 0; nf < 8; nf++) {
        const int col = nf * 8 + tig * 2;
        uint32_t hv, lv;
        psplit2(oacc[nf][0] * inv0, oacc[nf][1] * inv0, hv, lv);
        *(uint32_t*)&g_ctxh[base0 + col] = hv;
        *(uint32_t*)&g_ctxl[base0 + col] = lv;
        psplit2(oacc[nf][2] * inv1, oacc[nf][3] * inv1, hv, lv);
        *(uint32_t*)&g_ctxh[base1 + col] = hv;
        *(uint32_t*)&g_ctxl[base1 + col] = lv;
    }
}

// ---------------------------------------------------------------------------

extern "C" void kernel_launch(void* const* d_in, const int* in_sizes, int n_in,
                              void* d_out, int out_size) {
    const float* X   = (const float*)d_in[0];
    const float* Wq  = (const float*)d_in[1];
    const float* Wk  = (const float*)d_in[2];
    const float* Wv  = (const float*)d_in[3];
    const float* Wo  = (const float*)d_in[4];
    const float* bo  = (const float*)d_in[5];
    const float* Kbg = (const float*)d_in[6];
    const float* Vbg = (const float*)d_in[7];
    float* out = (float*)d_out;

    cudaFuncSetAttribute(attn_mma, cudaFuncAttributeMaxDynamicSharedMemorySize, SM_ATTN);

    split_x<<<MTOT * DD / 4 / 256, 256>>>(X);
    split_wT<<<dim3(DD / 32, DD / 32, 4), 256>>>(Wq, Wk, Wv, Wo);
    split_bg<<<dim3(BH * LQ * DHD / 4 / 256, 2), 256>>>(Kbg, Vbg);

    mma_qkv<<<dim3(DD / 128, MTOT / 128, 3), 256>>>();

    attn_mma<<<dim3(LQ / 64, BH), 128, SM_ATTN>>>();

    mma_out<<<dim3(DD / 128, MTOT / 128), 256>>>(bo, out);
}

// round 10
// speedup vs baseline: 2.4348x; 1.0244x over previous
#include <cuda_runtime.h>
#include <cuda_bf16.h>
#include <cstdint>

#define BQ 4
#define LQ 1024
#define DD 1280
#define HH 20
#define DHD 64
#define BH (BQ*HH)          // 80
#define MTOT (BQ*LQ)        // 4096
#define KV2 2048
#define ALPHA 0.48f
#define SCALE 0.125f        // 1/sqrt(64)

// ---------------------------------------------------------------------------
// Static device scratch (allocation-free)
// ---------------------------------------------------------------------------
__device__ __nv_bfloat16 g_xh[MTOT*DD],  g_xl[MTOT*DD];        // X  [m][k]
__device__ __nv_bfloat16 g_ctxh[MTOT*DD], g_ctxl[MTOT*DD];     // ctx [m][k]
__device__ __nv_bfloat16 g_wth[4*DD*DD], g_wtl[4*DD*DD];       // W^T [n][k]
__device__ __nv_bfloat16 g_qh[BH*LQ*DHD],  g_ql[BH*LQ*DHD];    // Q*SCALE split
__device__ __nv_bfloat16 g_kh[BH*KV2*DHD], g_kl[BH*KV2*DHD];   // K (self+bg)
__device__ __nv_bfloat16 g_vh[BH*KV2*DHD], g_vl[BH*KV2*DHD];   // V (self+bg)

// ---------------------------------------------------------------------------
// Split helpers: x = hi + lo, both bf16
// ---------------------------------------------------------------------------
__device__ __forceinline__ void split1(float x, unsigned& h, unsigned& l) {
    __nv_bfloat16 bh = __float2bfloat16_rn(x);
    float r = x - __bfloat162float(bh);
    __nv_bfloat16 bl = __float2bfloat16_rn(r);
    h = (unsigned)(*(unsigned short*)&bh);
    l = (unsigned)(*(unsigned short*)&bl);
}
__device__ __forceinline__ void split4(float4 v, uint2& hh, uint2& ll) {
    unsigned h0,l0,h1,l1,h2,l2,h3,l3;
    split1(v.x,h0,l0); split1(v.y,h1,l1); split1(v.z,h2,l2); split1(v.w,h3,l3);
    hh.x = h0 | (h1<<16);  hh.y = h2 | (h3<<16);
    ll.x = l0 | (l1<<16);  ll.y = l2 | (l3<<16);
}
__device__ __forceinline__ void psplit2(float x, float y, uint32_t& h, uint32_t& l) {
    unsigned hx,lx,hy,ly;
    split1(x,hx,lx); split1(y,hy,ly);
    h = hx | (hy << 16);
    l = lx | (ly << 16);
}

__device__ __forceinline__ uint32_t smem_u32(const void* p) {
    uint32_t a;
    asm("{ .reg .u64 t; cvta.to.shared.u64 t, %1; cvt.u32.u64 %0, t; }"
        : "=r"(a) : "l"(p));
    return a;
}

// cp.async helpers
__device__ __forceinline__ void cpa16(uint32_t s, const void* g) {
    asm volatile("cp.async.cg.shared.global [%0], [%1], 16;" :: "r"(s), "l"(g));
}
#define CP_COMMIT() asm volatile("cp.async.commit_group;" ::: "memory")
#define CP_WAIT1()  asm volatile("cp.async.wait_group 1;" ::: "memory")
#define CP_WAIT0()  asm volatile("cp.async.wait_group 0;" ::: "memory")

// ---------------------------------------------------------------------------
// split_x: X fp32 -> (g_xh, g_xl)
// ---------------------------------------------------------------------------
__global__ void __launch_bounds__(256) split_x(const float* __restrict__ X) {
    int i = blockIdx.x * 256 + threadIdx.x;           // float4 index
    float4 v = ((const float4*)X)[i];
    uint2 hh, ll;
    split4(v, hh, ll);
    ((uint2*)g_xh)[i] = hh;
    ((uint2*)g_xl)[i] = ll;
}

// ---------------------------------------------------------------------------
// split_bg: alpha * {Kbg,Vbg} fp32 -> bf16 splits at kv slots [1024, 2048)
// ---------------------------------------------------------------------------
__global__ void __launch_bounds__(256) split_bg(const float* __restrict__ Kbg,
                                                const float* __restrict__ Vbg) {
    const int z = blockIdx.y;
    const float* src = z ? Vbg : Kbg;
    __nv_bfloat16* dsth = z ? g_vh : g_kh;
    __nv_bfloat16* dstl = z ? g_vl : g_kl;
    size_t i = (size_t)blockIdx.x * 256 + threadIdx.x;
    float4 v = ((const float4*)src)[i];
    v.x *= ALPHA; v.y *= ALPHA; v.z *= ALPHA; v.w *= ALPHA;
    uint2 hh, ll;
    split4(v, hh, ll);
    size_t e = i * 4;
    size_t bh = e >> 16;
    size_t rem = e & 65535;
    size_t d = (bh << 17) + 65536 + rem;
    *(uint2*)&dsth[d] = hh;
    *(uint2*)&dstl[d] = ll;
}

// ---------------------------------------------------------------------------
// split_wT: W [k][n] fp32 -> W^T [n][k] bf16 hi/lo  (32x32 smem transpose)
// ---------------------------------------------------------------------------
__global__ void __launch_bounds__(256) split_wT(const float* __restrict__ Wq,
                                                const float* __restrict__ Wk,
                                                const float* __restrict__ Wv,
                                                const float* __restrict__ Wo) {
    const float* W = (blockIdx.z == 0) ? Wq : (blockIdx.z == 1) ? Wk
                   : (blockIdx.z == 2) ? Wv : Wo;
    __nv_bfloat16* dh = g_wth + (size_t)blockIdx.z * DD * DD;
    __nv_bfloat16* dl = g_wtl + (size_t)blockIdx.z * DD * DD;

    __shared__ float tile[32][33];
    const int t = threadIdx.x, tx = t & 31, ty = t >> 5;
    const int k0 = blockIdx.y * 32, n0 = blockIdx.x * 32;

    #pragma unroll
    for (int r = ty; r < 32; r += 8)
        tile[r][tx] = W[(size_t)(k0 + r) * DD + n0 + tx];
    __syncthreads();
    #pragma unroll
    for (int r = ty; r < 32; r += 8) {
        float v = tile[tx][r];
        unsigned h, l;
        split1(v, h, l);
        size_t idx = (size_t)(n0 + r) * DD + k0 + tx;
        dh[idx] = *(__nv_bfloat16*)&h;
        dl[idx] = *(__nv_bfloat16*)&l;
    }
}

// ---------------------------------------------------------------------------
// mma.sync primitives
// ---------------------------------------------------------------------------
__device__ __forceinline__ void ldmx4(uint32_t addr, uint32_t* r) {
    asm volatile("ldmatrix.sync.aligned.m8n8.x4.shared.b16 {%0,%1,%2,%3}, [%4];"
                 : "=r"(r[0]), "=r"(r[1]), "=r"(r[2]), "=r"(r[3]) : "r"(addr));
}
__device__ __forceinline__ void ldmx2(uint32_t addr, uint32_t* r) {
    asm volatile("ldmatrix.sync.aligned.m8n8.x2.shared.b16 {%0,%1}, [%2];"
                 : "=r"(r[0]), "=r"(r[1]) : "r"(addr));
}
__device__ __forceinline__ void ldmx2t(uint32_t addr, uint32_t* r) {
    asm volatile("ldmatrix.sync.aligned.m8n8.x2.trans.shared.b16 {%0,%1}, [%2];"
                 : "=r"(r[0]), "=r"(r[1]) : "r"(addr));
}
__device__ __forceinline__ void mma16816(float* c, const uint32_t* a, const uint32_t* b) {
    asm volatile(
        "mma.sync.aligned.m16n8k16.row.col.f32.bf16.bf16.f32 "
        "{%0,%1,%2,%3}, {%4,%5,%6,%7}, {%8,%9}, {%0,%1,%2,%3};"
        : "+f"(c[0]), "+f"(c[1]), "+f"(c[2]), "+f"(c[3])
        : "r"(a[0]), "r"(a[1]), "r"(a[2]), "r"(a[3]), "r"(b[0]), "r"(b[1]));
}

// ---------------------------------------------------------------------------
// GEMM core.  Block tile 128x128, K-chunk 32, 8 warps (2m x 4n), warp 64x32.
// 3-term split: AhBh + AhBl + AlBh.  smem row stride 80 B.
// cp.async 2-stage pipeline.
// ---------------------------------------------------------------------------
#define KC2 32
#define ROWB 80
#define SA_H 0
#define SA_L 10240
#define SB_H 20480
#define SB_L 30720
#define STG_GEMM 40960
#define SM_GEMM (2*STG_GEMM)
#define NCH (DD/KC2)

__device__ __forceinline__ void gemm_load_chunk(const __nv_bfloat16* __restrict__ Ah,
                                                const __nv_bfloat16* __restrict__ Al,
                                                const __nv_bfloat16* __restrict__ Bh,
                                                const __nv_bfloat16* __restrict__ Bl,
                                                uint32_t stg, int bm, int bn,
                                                int k0, int t) {
    #pragma unroll
    for (int i = 0; i < 4; i++) {
        int id = t + i * 256;
        int sel = id >> 9;
        int idx = id & 511;
        int row = idx >> 2, q = idx & 3;
        const __nv_bfloat16* src = (sel ? Al : Ah) + (size_t)(bm + row) * DD + k0 + q * 8;
        cpa16(stg + (sel ? SA_L : SA_H) + row * ROWB + q * 16, src);
    }
    #pragma unroll
    for (int i = 0; i < 4; i++) {
        int id = t + i * 256;
        int sel = id >> 9;
        int idx = id & 511;
        int row = idx >> 2, q = idx & 3;
        const __nv_bfloat16* src = (sel ? Bl : Bh) + (size_t)(bn + row) * DD + k0 + q * 8;
        cpa16(stg + (sel ? SB_L : SB_H) + row * ROWB + q * 16, src);
    }
}

__device__ __forceinline__ void mma_mainloop(const __nv_bfloat16* __restrict__ Ah,
                                             const __nv_bfloat16* __restrict__ Al,
                                             const __nv_bfloat16* __restrict__ Bh,
                                             const __nv_bfloat16* __restrict__ Bl,
                                             char* sm, int bm, int bn,
                                             float acc[4][4][4]) {
    const int t = threadIdx.x;
    const int wid = t >> 5, lane = t & 31;
    const int wm = (wid >> 2) * 64, wn = (wid & 3) * 32;
    const uint32_t smb = smem_u32(sm);

    const int a_r  = lane & 15;
    const int a_k8 = (lane >> 4) * 16;
    const int b_r  = lane & 7;
    const int b_k8 = ((lane >> 3) & 1) * 16;

    gemm_load_chunk(Ah, Al, Bh, Bl, smb, bm, bn, 0, t);
    CP_COMMIT();

    for (int c = 0; c < NCH; c++) {
        if (c + 1 < NCH) {
            gemm_load_chunk(Ah, Al, Bh, Bl, smb + ((c + 1) & 1) * STG_GEMM,
                            bm, bn, (c + 1) * KC2, t);
            CP_COMMIT();
            CP_WAIT1();
        } else {
            CP_WAIT0();
        }
        __syncthreads();
        const uint32_t stg = smb + (c & 1) * STG_GEMM;

        #pragma unroll
        for (int ks = 0; ks < KC2; ks += 16) {
            uint32_t ah[4][4], al[4][4], bh[4][2], bl[4][2];
            #pragma unroll
            for (int mf = 0; mf < 4; mf++) {
                uint32_t ra = (wm + mf * 16 + a_r) * ROWB + ks * 2 + a_k8;
                ldmx4(stg + SA_H + ra, ah[mf]);
                ldmx4(stg + SA_L + ra, al[mf]);
            }
            #pragma unroll
            for (int nf = 0; nf < 4; nf++) {
                uint32_t rb = (wn + nf * 8 + b_r) * ROWB + ks * 2 + b_k8;
                ldmx2(stg + SB_H + rb, bh[nf]);
                ldmx2(stg + SB_L + rb, bl[nf]);
            }
            #pragma unroll
            for (int mf = 0; mf < 4; mf++)
                #pragma unroll
                for (int nf = 0; nf < 4; nf++) {
                    mma16816(acc[mf][nf], ah[mf], bh[nf]);
                    mma16816(acc[mf][nf], ah[mf], bl[nf]);
                    mma16816(acc[mf][nf], al[mf], bh[nf]);
                }
        }
        __syncthreads();
    }
}

// QKV GEMM: epilogue splits directly to bf16 hi/lo in attention layout.
__global__ void __launch_bounds__(256) mma_qkv() {
    extern __shared__ char smd[];
    const int t = threadIdx.x, wid = t >> 5, lane = t & 31;
    const int wm = (wid >> 2) * 64, wn = (wid & 3) * 32;
    const int bm = blockIdx.y * 128, bn = blockIdx.x * 128;
    const int z = blockIdx.z;

    const __nv_bfloat16* Bh = g_wth + (size_t)z * DD * DD;
    const __nv_bfloat16* Bl = g_wtl + (size_t)z * DD * DD;
    __nv_bfloat16* dh_ = (z == 0) ? g_qh : (z == 1) ? g_kh : g_vh;
    __nv_bfloat16* dl_ = (z == 0) ? g_ql : (z == 1) ? g_kl : g_vl;
    const float mul = (z == 0) ? SCALE : 1.0f;
    const int shift = (z == 0) ? 16 : 17;

    float acc[4][4][4] = {};
    mma_mainloop(g_xh, g_xl, Bh, Bl, smd, bm, bn, acc);

    const int gid = lane >> 2, tig = lane & 3;
    #pragma unroll
    for (int mf = 0; mf < 4; mf++) {
        #pragma unroll
        for (int nf = 0; nf < 4; nf++) {
            int n = bn + wn + nf * 8 + tig * 2;
            int hh = n >> 6, dh = n & 63;
            #pragma unroll
            for (int half = 0; half < 2; half++) {
                int m = bm + wm + mf * 16 + gid + half * 8;
                int bb = m >> 10, lq2 = m & 1023;
                int bhh = bb * HH + hh;
                size_t idx = ((size_t)bhh << shift) + ((size_t)lq2 << 6) + dh;
                uint32_t hv, lv;
                psplit2(acc[mf][nf][half*2] * mul, acc[mf][nf][half*2+1] * mul, hv, lv);
                *(uint32_t*)&dh_[idx] = hv;
                *(uint32_t*)&dl_[idx] = lv;
            }
        }
    }
}

// Output GEMM: ctx (bf16 split) @ Wo^T + bias -> out
__global__ void __launch_bounds__(256) mma_out(const float* __restrict__ bo,
                                               float* __restrict__ out) {
    extern __shared__ char smd[];
    const int t = threadIdx.x, wid = t >> 5, lane = t & 31;
    const int wm = (wid >> 2) * 64, wn = (wid & 3) * 32;
    const int bm = blockIdx.y * 128, bn = blockIdx.x * 128;

    const __nv_bfloat16* Bh = g_wth + (size_t)3 * DD * DD;
    const __nv_bfloat16* Bl = g_wtl + (size_t)3 * DD * DD;

    float acc[4][4][4] = {};
    mma_mainloop(g_ctxh, g_ctxl, Bh, Bl, smd, bm, bn, acc);

    const int gid = lane >> 2, tig = lane & 3;
    #pragma unroll
    for (int mf = 0; mf < 4; mf++) {
        #pragma unroll
        for (int nf = 0; nf < 4; nf++) {
            int m = bm + wm + mf * 16 + gid;
            int n = bn + wn + nf * 8 + tig * 2;
            float2 bv = *(const float2*)(bo + n);
            *(float2*)(out + (size_t)m * DD + n) =
                make_float2(acc[mf][nf][0] + bv.x, acc[mf][nf][1] + bv.y);
            *(float2*)(out + (size_t)(m + 8) * DD + n) =
                make_float2(acc[mf][nf][2] + bv.x, acc[mf][nf][3] + bv.y);
        }
    }
}

// ---------------------------------------------------------------------------
// Tensor-core flash attention with cp.async 2-stage KV pipeline.
// Block = 128 threads (4 warps), 64 q rows, 32 kv tiles of 64.
// ---------------------------------------------------------------------------
#define SKB 144
#define AQH 0
#define AQL 9216
#define AKV 18432           // start of KV stages
#define STG_KV 36864        // Kh, Kl, Vh, Vl at +0, +9216, +18432, +27648
#define SM_ATTN (AKV + 2*STG_KV)   // 92160

__device__ __forceinline__ void attn_load_kv(uint32_t stg, size_t src0, int t) {
    #pragma unroll
    for (int i = 0; i < 16; i++) {
        int id = t + i * 128;        // 0..2047
        int arr = id >> 9;           // 0:Kh 1:Kl 2:Vh 3:Vl
        int idx = id & 511;
        int row = idx >> 3, q = idx & 7;
        const __nv_bfloat16* s =
            ((arr == 0) ? g_kh : (arr == 1) ? g_kl : (arr == 2) ? g_vh : g_vl)
            + src0 + row * 64 + q * 8;
        cpa16(stg + arr * 9216 + row * SKB + q * 16, s);
    }
}

__global__ void __launch_bounds__(128) attn_mma() {
    extern __shared__ char sm[];
    const uint32_t smb = smem_u32(sm);
    const int t = threadIdx.x, wid = t >> 5, lane = t & 31;
    const int gid = lane >> 2, tig = lane & 3;
    const int bh = blockIdx.y, q0 = blockIdx.x << 6;
    const int bb = bh / HH, hh = bh % HH;

    const size_t kvbase = (size_t)bh << 17;   // bh * 2048 * 64

    // prefetch KV tile 0 (stage 0)
    attn_load_kv(smb + AKV, kvbase, t);
    CP_COMMIT();

    // ---- load Q tile (64 rows x 64 bf16, hi+lo)
    {
        const __nv_bfloat16* qh = g_qh + ((size_t)bh << 16) + ((size_t)q0 << 6);
        const __nv_bfloat16* ql = g_ql + ((size_t)bh << 16) + ((size_t)q0 << 6);
        #pragma unroll
        for (int i = 0; i < 8; i++) {
            int id = t + i * 128;
            int sel = id >> 9;
            int idx = id & 511;
            int row = idx >> 3, q = idx & 7;
            const __nv_bfloat16* src = (sel ? ql : qh) + row * 64 + q * 8;
            uint4 v = *(const uint4*)src;
            *(uint4*)(sm + (sel ? AQL : AQH) + row * SKB + q * 16) = v;
        }
    }

    float oacc[8][4] = {};
    float mrow[2] = {-1e30f, -1e30f};
    float lrow[2] = {0.0f, 0.0f};

    const int a_r  = lane & 15;
    const int a_k16 = (lane >> 4) * 16;
    const int b_r  = lane & 7;
    const int b_k16 = ((lane >> 3) & 1) * 16;
    const int v_r  = (lane & 7) + ((lane >> 3) & 1) * 8;

    const uint32_t qb_h = smb + AQH + (wid * 16 + a_r) * SKB + a_k16;
    const uint32_t qb_l = smb + AQL + (wid * 16 + a_r) * SKB + a_k16;

    for (int tile = 0; tile < 32; tile++) {
        if (tile + 1 < 32) {
            attn_load_kv(smb + AKV + ((tile + 1) & 1) * STG_KV,
                         kvbase + ((size_t)((tile + 1) << 6) << 6), t);
            CP_COMMIT();
            CP_WAIT1();
        } else {
            CP_WAIT0();
        }
        __syncthreads();
        const uint32_t kstg = smb + AKV + (tile & 1) * STG_KV;
        const uint32_t vstg = kstg + 18432;

        // ---- S = Q K^T
        float sacc[8][4] = {};
        #pragma unroll
        for (int ks = 0; ks < 4; ks++) {
            uint32_t ah[4], al[4];
            ldmx4(qb_h + ks * 32, ah);
            ldmx4(qb_l + ks * 32, al);
            #pragma unroll
            for (int nf = 0; nf < 8; nf++) {
                uint32_t kh2[2], kl2[2];
                uint32_t rb = kstg + (nf * 8 + b_r) * SKB + ks * 32 + b_k16;
                ldmx2(rb, kh2);
                ldmx2(rb + 9216, kl2);
                mma16816(sacc[nf], ah, kh2);
                mma16816(sacc[nf], ah, kl2);
                mma16816(sacc[nf], al, kh2);
            }
        }

        // ---- online softmax (rows gid, gid+8)
        #pragma unroll
        for (int rr = 0; rr < 2; rr++) {
            const int o0 = rr * 2;
            float mx = -1e30f;
            #pragma unroll
            for (int nf = 0; nf < 8; nf++)
                mx = fmaxf(mx, fmaxf(sacc[nf][o0], sacc[nf][o0 + 1]));
            mx = fmaxf(mx, __shfl_xor_sync(0xffffffffu, mx, 1));
            mx = fmaxf(mx, __shfl_xor_sync(0xffffffffu, mx, 2));
            float mn = fmaxf(mrow[rr], mx);
            float corr = __expf(mrow[rr] - mn);
            mrow[rr] = mn;
            float rs = 0.0f;
            #pragma unroll
            for (int nf = 0; nf < 8; nf++) {
                float p0 = __expf(sacc[nf][o0] - mn);
                float p1 = __expf(sacc[nf][o0 + 1] - mn);
                sacc[nf][o0] = p0; sacc[nf][o0 + 1] = p1;
                rs += p0 + p1;
            }
            rs += __shfl_xor_sync(0xffffffffu, rs, 1);
            rs += __shfl_xor_sync(0xffffffffu, rs, 2);
            lrow[rr] = lrow[rr] * corr + rs;
            #pragma unroll
            for (int nf = 0; nf < 8; nf++) {
                oacc[nf][o0]     *= corr;
                oacc[nf][o0 + 1] *= corr;
            }
        }

        // ---- O += P V
        #pragma unroll
        for (int ks = 0; ks < 4; ks++) {
            const float* f0 = sacc[2 * ks];
            const float* f1 = sacc[2 * ks + 1];
            uint32_t ph[4], pl[4];
            psplit2(f0[0], f0[1], ph[0], pl[0]);
            psplit2(f0[2], f0[3], ph[1], pl[1]);
            psplit2(f1[0], f1[1], ph[2], pl[2]);
            psplit2(f1[2], f1[3], ph[3], pl[3]);
            #pragma unroll
            for (int nf = 0; nf < 8; nf++) {
                uint32_t vh2[2], vl2[2];
                uint32_t rv = vstg + (ks * 16 + v_r) * SKB + nf * 16;
                ldmx2t(rv, vh2);
                ldmx2t(rv + 9216, vl2);
                mma16816(oacc[nf], ph, vh2);
                mma16816(oacc[nf], ph, vl2);
                mma16816(oacc[nf], pl, vh2);
            }
        }
        __syncthreads();
    }

    // ---- epilogue: normalize, split, write ctx [B, L, D]
    const float inv0 = 1.0f / lrow[0];
    const float inv1 = 1.0f / lrow[1];
    const int lq0 = q0 + wid * 16 + gid;
    const size_t base0 = ((size_t)(bb * LQ + lq0)) * DD + hh * 64;
    const size_t base1 = ((size_t)(bb * LQ + lq0 + 8)) * DD + hh * 64;
    #pragma unroll
    for (int nf = 0; nf < 8; nf++) {
        const int col = nf * 8 + tig * 2;
        uint32_t hv, lv;
        psplit2(oacc[nf][0] * inv0, oacc[nf][1] * inv0, hv, lv);
        *(uint32_t*)&g_ctxh[base0 + col] = hv;
        *(uint32_t*)&g_ctxl[base0 + col] = lv;
        psplit2(oacc[nf][2] * inv1, oacc[nf][3] * inv1, hv, lv);
        *(uint32_t*)&g_ctxh[base1 + col] = hv;
        *(uint32_t*)&g_ctxl[base1 + col] = lv;
    }
}

// ---------------------------------------------------------------------------

extern "C" void kernel_launch(void* const* d_in, const int* in_sizes, int n_in,
                              void* d_out, int out_size) {
    const float* X   = (const float*)d_in[0];
    const float* Wq  = (const float*)d_in[1];
    const float* Wk  = (const float*)d_in[2];
    const float* Wv  = (const float*)d_in[3];
    const float* Wo  = (const float*)d_in[4];
    const float* bo  = (const float*)d_in[5];
    const float* Kbg = (const float*)d_in[6];
    const float* Vbg = (const float*)d_in[7];
    float* out = (float*)d_out;

    cudaFuncSetAttribute(mma_qkv, cudaFuncAttributeMaxDynamicSharedMemorySize, SM_GEMM);
    cudaFuncSetAttribute(mma_out, cudaFuncAttributeMaxDynamicSharedMemorySize, SM_GEMM);
    cudaFuncSetAttribute(attn_mma, cudaFuncAttributeMaxDynamicSharedMemorySize, SM_ATTN);

    split_x<<<MTOT * DD / 4 / 256, 256>>>(X);
    split_wT<<<dim3(DD / 32, DD / 32, 4), 256>>>(Wq, Wk, Wv, Wo);
    split_bg<<<dim3(BH * LQ * DHD / 4 / 256, 2), 256>>>(Kbg, Vbg);

    mma_qkv<<<dim3(DD / 128, MTOT / 128, 3), 256, SM_GEMM>>>();

    attn_mma<<<dim3(LQ / 64, BH), 128, SM_ATTN>>>();

    mma_out<<<dim3(DD / 128, MTOT / 128), 256, SM_GEMM>>>(bo, out);
}

// round 11
// speedup vs baseline: 3.0014x; 1.2327x over previous
#include <cuda_runtime.h>
#include <cuda_bf16.h>
#include <cstdint>

#define BQ 4
#define LQ 1024
#define DD 1280
#define HH 20
#define DHD 64
#define BH (BQ*HH)          // 80
#define MTOT (BQ*LQ)        // 4096
#define KV2 2048
#define ALPHA 0.48f
#define SCALE 0.125f        // 1/sqrt(64)

// ---------------------------------------------------------------------------
// Static device scratch (allocation-free)
// ---------------------------------------------------------------------------
__device__ __nv_bfloat16 g_xh[MTOT*DD],  g_xl[MTOT*DD];        // X  [m][k]
__device__ __nv_bfloat16 g_ctxh[MTOT*DD], g_ctxl[MTOT*DD];     // ctx [m][k]
__device__ __nv_bfloat16 g_wth[4*DD*DD], g_wtl[4*DD*DD];       // W^T [n][k]
__device__ __nv_bfloat16 g_qh[BH*LQ*DHD],  g_ql[BH*LQ*DHD];    // Q*SCALE split
__device__ __nv_bfloat16 g_kh[BH*KV2*DHD], g_kl[BH*KV2*DHD];   // K (self+bg)
__device__ __nv_bfloat16 g_vh[BH*KV2*DHD], g_vl[BH*KV2*DHD];   // V (self+bg)

// ---------------------------------------------------------------------------
// Split helpers: x = hi + lo, both bf16
// ---------------------------------------------------------------------------
__device__ __forceinline__ void split1(float x, unsigned& h, unsigned& l) {
    __nv_bfloat16 bh = __float2bfloat16_rn(x);
    float r = x - __bfloat162float(bh);
    __nv_bfloat16 bl = __float2bfloat16_rn(r);
    h = (unsigned)(*(unsigned short*)&bh);
    l = (unsigned)(*(unsigned short*)&bl);
}
__device__ __forceinline__ void split4(float4 v, uint2& hh, uint2& ll) {
    unsigned h0,l0,h1,l1,h2,l2,h3,l3;
    split1(v.x,h0,l0); split1(v.y,h1,l1); split1(v.z,h2,l2); split1(v.w,h3,l3);
    hh.x = h0 | (h1<<16);  hh.y = h2 | (h3<<16);
    ll.x = l0 | (l1<<16);  ll.y = l2 | (l3<<16);
}
__device__ __forceinline__ void psplit2(float x, float y, uint32_t& h, uint32_t& l) {
    unsigned hx,lx,hy,ly;
    split1(x,hx,lx); split1(y,hy,ly);
    h = hx | (hy << 16);
    l = lx | (ly << 16);
}

__device__ __forceinline__ uint32_t smem_u32(const void* p) {
    uint32_t a;
    asm("{ .reg .u64 t; cvta.to.shared.u64 t, %1; cvt.u32.u64 %0, t; }"
        : "=r"(a) : "l"(p));
    return a;
}

// swizzles (unpadded, conflict-free ldmatrix)
__device__ __forceinline__ uint32_t sw64(uint32_t o)  { return o ^ ((o >> 3) & 0x30); }
__device__ __forceinline__ uint32_t sw128(uint32_t o) { return o ^ ((o >> 3) & 0x70); }

// cp.async helpers
__device__ __forceinline__ void cpa16(uint32_t s, const void* g) {
    asm volatile("cp.async.cg.shared.global [%0], [%1], 16;" :: "r"(s), "l"(g));
}
#define CP_COMMIT() asm volatile("cp.async.commit_group;" ::: "memory")
#define CP_WAIT1()  asm volatile("cp.async.wait_group 1;" ::: "memory")
#define CP_WAIT0()  asm volatile("cp.async.wait_group 0;" ::: "memory")

// ---------------------------------------------------------------------------
// split_x: X fp32 -> (g_xh, g_xl)
// ---------------------------------------------------------------------------
__global__ void __launch_bounds__(256) split_x(const float* __restrict__ X) {
    int i = blockIdx.x * 256 + threadIdx.x;
    float4 v = ((const float4*)X)[i];
    uint2 hh, ll;
    split4(v, hh, ll);
    ((uint2*)g_xh)[i] = hh;
    ((uint2*)g_xl)[i] = ll;
}

// ---------------------------------------------------------------------------
// split_bg: alpha * {Kbg,Vbg} fp32 -> bf16 splits at kv slots [1024, 2048)
// ---------------------------------------------------------------------------
__global__ void __launch_bounds__(256) split_bg(const float* __restrict__ Kbg,
                                                const float* __restrict__ Vbg) {
    const int z = blockIdx.y;
    const float* src = z ? Vbg : Kbg;
    __nv_bfloat16* dsth = z ? g_vh : g_kh;
    __nv_bfloat16* dstl = z ? g_vl : g_kl;
    size_t i = (size_t)blockIdx.x * 256 + threadIdx.x;
    float4 v = ((const float4*)src)[i];
    v.x *= ALPHA; v.y *= ALPHA; v.z *= ALPHA; v.w *= ALPHA;
    uint2 hh, ll;
    split4(v, hh, ll);
    size_t e = i * 4;
    size_t bh = e >> 16;
    size_t rem = e & 65535;
    size_t d = (bh << 17) + 65536 + rem;
    *(uint2*)&dsth[d] = hh;
    *(uint2*)&dstl[d] = ll;
}

// ---------------------------------------------------------------------------
// split_wT: W [k][n] fp32 -> W^T [n][k] bf16 hi/lo  (32x32 smem transpose)
// ---------------------------------------------------------------------------
__global__ void __launch_bounds__(256) split_wT(const float* __restrict__ Wq,
                                                const float* __restrict__ Wk,
                                                const float* __restrict__ Wv,
                                                const float* __restrict__ Wo) {
    const float* W = (blockIdx.z == 0) ? Wq : (blockIdx.z == 1) ? Wk
                   : (blockIdx.z == 2) ? Wv : Wo;
    __nv_bfloat16* dh = g_wth + (size_t)blockIdx.z * DD * DD;
    __nv_bfloat16* dl = g_wtl + (size_t)blockIdx.z * DD * DD;

    __shared__ float tile[32][33];
    const int t = threadIdx.x, tx = t & 31, ty = t >> 5;
    const int k0 = blockIdx.y * 32, n0 = blockIdx.x * 32;

    #pragma unroll
    for (int r = ty; r < 32; r += 8)
        tile[r][tx] = W[(size_t)(k0 + r) * DD + n0 + tx];
    __syncthreads();
    #pragma unroll
    for (int r = ty; r < 32; r += 8) {
        float v = tile[tx][r];
        unsigned h, l;
        split1(v, h, l);
        size_t idx = (size_t)(n0 + r) * DD + k0 + tx;
        dh[idx] = *(__nv_bfloat16*)&h;
        dl[idx] = *(__nv_bfloat16*)&l;
    }
}

// ---------------------------------------------------------------------------
// mma.sync primitives
// ---------------------------------------------------------------------------
__device__ __forceinline__ void ldmx4(uint32_t addr, uint32_t* r) {
    asm volatile("ldmatrix.sync.aligned.m8n8.x4.shared.b16 {%0,%1,%2,%3}, [%4];"
                 : "=r"(r[0]), "=r"(r[1]), "=r"(r[2]), "=r"(r[3]) : "r"(addr));
}
__device__ __forceinline__ void ldmx2(uint32_t addr, uint32_t* r) {
    asm volatile("ldmatrix.sync.aligned.m8n8.x2.shared.b16 {%0,%1}, [%2];"
                 : "=r"(r[0]), "=r"(r[1]) : "r"(addr));
}
__device__ __forceinline__ void ldmx2t(uint32_t addr, uint32_t* r) {
    asm volatile("ldmatrix.sync.aligned.m8n8.x2.trans.shared.b16 {%0,%1}, [%2];"
                 : "=r"(r[0]), "=r"(r[1]) : "r"(addr));
}
__device__ __forceinline__ void mma16816(float* c, const uint32_t* a, const uint32_t* b) {
    asm volatile(
        "mma.sync.aligned.m16n8k16.row.col.f32.bf16.bf16.f32 "
        "{%0,%1,%2,%3}, {%4,%5,%6,%7}, {%8,%9}, {%0,%1,%2,%3};"
        : "+f"(c[0]), "+f"(c[1]), "+f"(c[2]), "+f"(c[3])
        : "r"(a[0]), "r"(a[1]), "r"(a[2]), "r"(a[3]), "r"(b[0]), "r"(b[1]));
}

// ---------------------------------------------------------------------------
// GEMM core.  Block tile 128x128, K-chunk 32, 8 warps (2m x 4n), warp 64x32.
// 3-term split: AhBh + AhBl + AlBh.  Unpadded SW64 tiles, cp.async 2-stage.
// ---------------------------------------------------------------------------
#define KC2 32
#define SA_H 0
#define SA_L 8192
#define SB_H 16384
#define SB_L 24576
#define STG_GEMM 32768
#define SM_GEMM (2*STG_GEMM)
#define NCH (DD/KC2)

__device__ __forceinline__ void gemm_load_chunk(const __nv_bfloat16* __restrict__ Ah,
                                                const __nv_bfloat16* __restrict__ Al,
                                                const __nv_bfloat16* __restrict__ Bh,
                                                const __nv_bfloat16* __restrict__ Bl,
                                                uint32_t stg, int bm, int bn,
                                                int k0, int t) {
    #pragma unroll
    for (int i = 0; i < 8; i++) {
        int id = t + i * 256;            // 0..2047 chunks of 16 B
        int arr = id >> 9;               // 0:Ah 1:Al 2:Bh 3:Bl
        int idx = id & 511;
        int row = idx >> 2, c16 = idx & 3;
        const __nv_bfloat16* base =
            (arr == 0) ? Ah : (arr == 1) ? Al : (arr == 2) ? Bh : Bl;
        int rbase = (arr < 2) ? bm : bn;
        const __nv_bfloat16* src = base + (size_t)(rbase + row) * DD + k0 + c16 * 8;
        cpa16(stg + arr * 8192 + sw64(row * 64 + c16 * 16), src);
    }
}

__device__ __forceinline__ void mma_mainloop(const __nv_bfloat16* __restrict__ Ah,
                                             const __nv_bfloat16* __restrict__ Al,
                                             const __nv_bfloat16* __restrict__ Bh,
                                             const __nv_bfloat16* __restrict__ Bl,
                                             char* sm, int bm, int bn,
                                             float acc[4][4][4]) {
    const int t = threadIdx.x;
    const int wid = t >> 5, lane = t & 31;
    const int wm = (wid >> 2) * 64, wn = (wid & 3) * 32;
    const uint32_t smb = smem_u32(sm);

    const int a_r  = lane & 15;
    const int a_k8 = (lane >> 4) * 16;
    const int b_r  = lane & 7;
    const int b_k8 = ((lane >> 3) & 1) * 16;

    gemm_load_chunk(Ah, Al, Bh, Bl, smb, bm, bn, 0, t);
    CP_COMMIT();

    for (int c = 0; c < NCH; c++) {
        if (c + 1 < NCH) {
            gemm_load_chunk(Ah, Al, Bh, Bl, smb + ((c + 1) & 1) * STG_GEMM,
                            bm, bn, (c + 1) * KC2, t);
            CP_COMMIT();
            CP_WAIT1();
        } else {
            CP_WAIT0();
        }
        __syncthreads();
        const uint32_t stg = smb + (c & 1) * STG_GEMM;

        #pragma unroll
        for (int ks = 0; ks < KC2; ks += 16) {
            uint32_t ah[4][4], al[4][4];
            #pragma unroll
            for (int mf = 0; mf < 4; mf++) {
                uint32_t ra = sw64((wm + mf * 16 + a_r) * 64 + ks * 2 + a_k8);
                ldmx4(stg + SA_H + ra, ah[mf]);
                ldmx4(stg + SA_L + ra, al[mf]);
            }
            #pragma unroll
            for (int nf = 0; nf < 4; nf++) {
                uint32_t bh[2], bl[2];
                uint32_t rb = sw64((wn + nf * 8 + b_r) * 64 + ks * 2 + b_k8);
                ldmx2(stg + SB_H + rb, bh);
                ldmx2(stg + SB_L + rb, bl);
                #pragma unroll
                for (int mf = 0; mf < 4; mf++) {
                    mma16816(acc[mf][nf], ah[mf], bh);
                    mma16816(acc[mf][nf], ah[mf], bl);
                    mma16816(acc[mf][nf], al[mf], bh);
                }
            }
        }
        __syncthreads();
    }
}

// QKV GEMM: epilogue splits directly to bf16 hi/lo in attention layout.
__global__ void __launch_bounds__(256, 2) mma_qkv() {
    extern __shared__ char smd[];
    const int t = threadIdx.x, wid = t >> 5, lane = t & 31;
    const int wm = (wid >> 2) * 64, wn = (wid & 3) * 32;
    const int bm = blockIdx.y * 128, bn = blockIdx.x * 128;
    const int z = blockIdx.z;

    const __nv_bfloat16* Bh = g_wth + (size_t)z * DD * DD;
    const __nv_bfloat16* Bl = g_wtl + (size_t)z * DD * DD;
    __nv_bfloat16* dh_ = (z == 0) ? g_qh : (z == 1) ? g_kh : g_vh;
    __nv_bfloat16* dl_ = (z == 0) ? g_ql : (z == 1) ? g_kl : g_vl;
    const float mul = (z == 0) ? SCALE : 1.0f;
    const int shift = (z == 0) ? 16 : 17;

    float acc[4][4][4] = {};
    mma_mainloop(g_xh, g_xl, Bh, Bl, smd, bm, bn, acc);

    const int gid = lane >> 2, tig = lane & 3;
    #pragma unroll
    for (int mf = 0; mf < 4; mf++) {
        #pragma unroll
        for (int nf = 0; nf < 4; nf++) {
            int n = bn + wn + nf * 8 + tig * 2;
            int hh = n >> 6, dh = n & 63;
            #pragma unroll
            for (int half = 0; half < 2; half++) {
                int m = bm + wm + mf * 16 + gid + half * 8;
                int bb = m >> 10, lq2 = m & 1023;
                int bhh = bb * HH + hh;
                size_t idx = ((size_t)bhh << shift) + ((size_t)lq2 << 6) + dh;
                uint32_t hv, lv;
                psplit2(acc[mf][nf][half*2] * mul, acc[mf][nf][half*2+1] * mul, hv, lv);
                *(uint32_t*)&dh_[idx] = hv;
                *(uint32_t*)&dl_[idx] = lv;
            }
        }
    }
}

// Output GEMM: ctx (bf16 split) @ Wo^T + bias -> out
__global__ void __launch_bounds__(256, 2) mma_out(const float* __restrict__ bo,
                                                  float* __restrict__ out) {
    extern __shared__ char smd[];
    const int t = threadIdx.x, wid = t >> 5, lane = t & 31;
    const int wm = (wid >> 2) * 64, wn = (wid & 3) * 32;
    const int bm = blockIdx.y * 128, bn = blockIdx.x * 128;

    const __nv_bfloat16* Bh = g_wth + (size_t)3 * DD * DD;
    const __nv_bfloat16* Bl = g_wtl + (size_t)3 * DD * DD;

    float acc[4][4][4] = {};
    mma_mainloop(g_ctxh, g_ctxl, Bh, Bl, smd, bm, bn, acc);

    const int gid = lane >> 2, tig = lane & 3;
    #pragma unroll
    for (int mf = 0; mf < 4; mf++) {
        #pragma unroll
        for (int nf = 0; nf < 4; nf++) {
            int m = bm + wm + mf * 16 + gid;
            int n = bn + wn + nf * 8 + tig * 2;
            float2 bv = *(const float2*)(bo + n);
            *(float2*)(out + (size_t)m * DD + n) =
                make_float2(acc[mf][nf][0] + bv.x, acc[mf][nf][1] + bv.y);
            *(float2*)(out + (size_t)(m + 8) * DD + n) =
                make_float2(acc[mf][nf][2] + bv.x, acc[mf][nf][3] + bv.y);
        }
    }
}

// ---------------------------------------------------------------------------
// Tensor-core flash attention, 256 threads (8 warps), 128-q-row tile.
// Unpadded SW128 tiles, cp.async 2-stage KV pipeline, 32 kv tiles of 64.
// ---------------------------------------------------------------------------
#define AQH 0
#define AQL 16384
#define AKV 32768           // stages: Kh +0, Kl +8192, Vh +16384, Vl +24576
#define STG_KV 32768
#define SM_ATTN (AKV + 2*STG_KV)   // 98304

__device__ __forceinline__ void attn_load_kv(uint32_t stg, size_t src0, int t) {
    #pragma unroll
    for (int i = 0; i < 8; i++) {
        int id = t + i * 256;        // 0..2047
        int arr = id >> 9;           // 0:Kh 1:Kl 2:Vh 3:Vl
        int idx = id & 511;
        int row = idx >> 3, c16 = idx & 7;
        const __nv_bfloat16* s =
            ((arr == 0) ? g_kh : (arr == 1) ? g_kl : (arr == 2) ? g_vh : g_vl)
            + src0 + row * 64 + c16 * 8;
        cpa16(stg + arr * 8192 + sw128(row * 128 + c16 * 16), s);
    }
}

__global__ void __launch_bounds__(256, 2) attn_mma() {
    extern __shared__ char sm[];
    const uint32_t smb = smem_u32(sm);
    const int t = threadIdx.x, wid = t >> 5, lane = t & 31;
    const int gid = lane >> 2, tig = lane & 3;
    const int bh = blockIdx.y, q0 = blockIdx.x << 7;
    const int bb = bh / HH, hh = bh % HH;

    const size_t kvbase = (size_t)bh << 17;   // bh * 2048 * 64

    // prefetch KV tile 0 (stage 0)
    attn_load_kv(smb + AKV, kvbase, t);
    CP_COMMIT();

    // ---- load Q tile (128 rows x 64 bf16, hi+lo), SW128
    {
        const __nv_bfloat16* qh = g_qh + ((size_t)bh << 16) + ((size_t)q0 << 6);
        const __nv_bfloat16* ql = g_ql + ((size_t)bh << 16) + ((size_t)q0 << 6);
        #pragma unroll
        for (int i = 0; i < 8; i++) {
            int id = t + i * 256;        // 0..2047
            int sel = id >> 10;
            int idx = id & 1023;
            int row = idx >> 3, c16 = idx & 7;
            const __nv_bfloat16* src = (sel ? ql : qh) + row * 64 + c16 * 8;
            uint4 v = *(const uint4*)src;
            *(uint4*)(sm + (sel ? AQL : AQH) + sw128(row * 128 + c16 * 16)) = v;
        }
    }

    float oacc[8][4] = {};
    float mrow[2] = {-1e30f, -1e30f};
    float lrow[2] = {0.0f, 0.0f};

    const int a_r  = lane & 15;
    const int a_k16 = (lane >> 4) * 16;
    const int b_r  = lane & 7;
    const int b_k16 = ((lane >> 3) & 1) * 16;
    const int v_r  = (lane & 7) + ((lane >> 3) & 1) * 8;

    for (int tile = 0; tile < 32; tile++) {
        if (tile + 1 < 32) {
            attn_load_kv(smb + AKV + ((tile + 1) & 1) * STG_KV,
                         kvbase + ((size_t)((tile + 1) << 6) << 6), t);
            CP_COMMIT();
            CP_WAIT1();
        } else {
            CP_WAIT0();
        }
        __syncthreads();
        const uint32_t kstg = smb + AKV + (tile & 1) * STG_KV;
        const uint32_t vstg = kstg + 16384;

        // ---- S = Q K^T
        float sacc[8][4] = {};
        #pragma unroll
        for (int ks = 0; ks < 4; ks++) {
            uint32_t ah[4], al[4];
            uint32_t ra = sw128((wid * 16 + a_r) * 128 + ks * 32 + a_k16);
            ldmx4(smb + AQH + ra, ah);
            ldmx4(smb + AQL + ra, al);
            #pragma unroll
            for (int nf = 0; nf < 8; nf++) {
                uint32_t kh2[2], kl2[2];
                uint32_t rb = sw128((nf * 8 + b_r) * 128 + ks * 32 + b_k16);
                ldmx2(kstg + rb, kh2);
                ldmx2(kstg + 8192 + rb, kl2);
                mma16816(sacc[nf], ah, kh2);
                mma16816(sacc[nf], ah, kl2);
                mma16816(sacc[nf], al, kh2);
            }
        }

        // ---- online softmax (rows gid, gid+8 within warp's 16 rows)
        #pragma unroll
        for (int rr = 0; rr < 2; rr++) {
            const int o0 = rr * 2;
            float mx = -1e30f;
            #pragma unroll
            for (int nf = 0; nf < 8; nf++)
                mx = fmaxf(mx, fmaxf(sacc[nf][o0], sacc[nf][o0 + 1]));
            mx = fmaxf(mx, __shfl_xor_sync(0xffffffffu, mx, 1));
            mx = fmaxf(mx, __shfl_xor_sync(0xffffffffu, mx, 2));
            float mn = fmaxf(mrow[rr], mx);
            float corr = __expf(mrow[rr] - mn);
            mrow[rr] = mn;
            float rs = 0.0f;
            #pragma unroll
            for (int nf = 0; nf < 8; nf++) {
                float p0 = __expf(sacc[nf][o0] - mn);
                float p1 = __expf(sacc[nf][o0 + 1] - mn);
                sacc[nf][o0] = p0; sacc[nf][o0 + 1] = p1;
                rs += p0 + p1;
            }
            rs += __shfl_xor_sync(0xffffffffu, rs, 1);
            rs += __shfl_xor_sync(0xffffffffu, rs, 2);
            lrow[rr] = lrow[rr] * corr + rs;
            #pragma unroll
            for (int nf = 0; nf < 8; nf++) {
                oacc[nf][o0]     *= corr;
                oacc[nf][o0 + 1] *= corr;
            }
        }

        // ---- O += P V
        #pragma unroll
        for (int ks = 0; ks < 4; ks++) {
            const float* f0 = sacc[2 * ks];
            const float* f1 = sacc[2 * ks + 1];
            uint32_t ph[4], pl[4];
            psplit2(f0[0], f0[1], ph[0], pl[0]);
            psplit2(f0[2], f0[3], ph[1], pl[1]);
            psplit2(f1[0], f1[1], ph[2], pl[2]);
            psplit2(f1[2], f1[3], ph[3], pl[3]);
            #pragma unroll
            for (int nf = 0; nf < 8; nf++) {
                uint32_t vh2[2], vl2[2];
                uint32_t rv = sw128((ks * 16 + v_r) * 128 + nf * 16);
                ldmx2t(vstg + rv, vh2);
                ldmx2t(vstg + 8192 + rv, vl2);
                mma16816(oacc[nf], ph, vh2);
                mma16816(oacc[nf], ph, vl2);
                mma16816(oacc[nf], pl, vh2);
            }
        }
        __syncthreads();
    }

    // ---- epilogue: normalize, split, write ctx [B, L, D]
    const float inv0 = 1.0f / lrow[0];
    const float inv1 = 1.0f / lrow[1];
    const int lq0 = q0 + wid * 16 + gid;
    const size_t base0 = ((size_t)(bb * LQ + lq0)) * DD + hh * 64;
    const size_t base1 = ((size_t)(bb * LQ + lq0 + 8)) * DD + hh * 64;
    #pragma unroll
    for (int nf = 0; nf < 8; nf++) {
        const int col = nf * 8 + tig * 2;
        uint32_t hv, lv;
        psplit2(oacc[nf][0] * inv0, oacc[nf][1] * inv0, hv, lv);
        *(uint32_t*)&g_ctxh[base0 + col] = hv;
        *(uint32_t*)&g_ctxl[base0 + col] = lv;
        psplit2(oacc[nf][2] * inv1, oacc[nf][3] * inv1, hv, lv);
        *(uint32_t*)&g_ctxh[base1 + col] = hv;
        *(uint32_t*)&g_ctxl[base1 + col] = lv;
    }
}

// ---------------------------------------------------------------------------

extern "C" void kernel_launch(void* const* d_in, const int* in_sizes, int n_in,
                              void* d_out, int out_size) {
    const float* X   = (const float*)d_in[0];
    const float* Wq  = (const float*)d_in[1];
    const float* Wk  = (const float*)d_in[2];
    const float* Wv  = (const float*)d_in[3];
    const float* Wo  = (const float*)d_in[4];
    const float* bo  = (const float*)d_in[5];
    const float* Kbg = (const float*)d_in[6];
    const float* Vbg = (const float*)d_in[7];
    float* out = (float*)d_out;

    cudaFuncSetAttribute(mma_qkv, cudaFuncAttributeMaxDynamicSharedMemorySize, SM_GEMM);
    cudaFuncSetAttribute(mma_out, cudaFuncAttributeMaxDynamicSharedMemorySize, SM_GEMM);
    cudaFuncSetAttribute(attn_mma, cudaFuncAttributeMaxDynamicSharedMemorySize, SM_ATTN);

    split_x<<<MTOT * DD / 4 / 256, 256>>>(X);
    split_wT<<<dim3(DD / 32, DD / 32, 4), 256>>>(Wq, Wk, Wv, Wo);
    split_bg<<<dim3(BH * LQ * DHD / 4 / 256, 2), 256>>>(Kbg, Vbg);

    mma_qkv<<<dim3(DD / 128, MTOT / 128, 3), 256, SM_GEMM>>>();

    attn_mma<<<dim3(LQ / 128, BH), 256, SM_ATTN>>>();

    mma_out<<<dim3(DD / 128, MTOT / 128), 256, SM_GEMM>>>(bo, out);
}

// round 13
// speedup vs baseline: 3.0307x; 1.0098x over previous
#include <cuda_runtime.h>
#include <cuda_bf16.h>
#include <cstdint>

#define BQ 4
#define LQ 1024
#define DD 1280
#define HH 20
#define DHD 64
#define BH (BQ*HH)          // 80
#define MTOT (BQ*LQ)        // 4096
#define KV2 2048
#define ALPHA 0.48f
#define SCALE 0.125f        // 1/sqrt(64)

// ---------------------------------------------------------------------------
// Static device scratch (allocation-free)
// ---------------------------------------------------------------------------
__device__ __nv_bfloat16 g_xh[MTOT*DD],  g_xl[MTOT*DD];        // X  [m][k]
__device__ __nv_bfloat16 g_ctxh[MTOT*DD], g_ctxl[MTOT*DD];     // ctx [m][k]
__device__ __nv_bfloat16 g_wth[4*DD*DD], g_wtl[4*DD*DD];       // W^T [n][k]
__device__ __nv_bfloat16 g_qh[BH*LQ*DHD],  g_ql[BH*LQ*DHD];    // Q*SCALE split
__device__ __nv_bfloat16 g_kh[BH*KV2*DHD], g_kl[BH*KV2*DHD];   // K (self+bg)
__device__ __nv_bfloat16 g_vh[BH*KV2*DHD], g_vl[BH*KV2*DHD];   // V (self+bg)

// ---------------------------------------------------------------------------
// Split helpers: x = hi + lo, both bf16
// ---------------------------------------------------------------------------
__device__ __forceinline__ void split1(float x, unsigned& h, unsigned& l) {
    __nv_bfloat16 bh = __float2bfloat16_rn(x);
    float r = x - __bfloat162float(bh);
    __nv_bfloat16 bl = __float2bfloat16_rn(r);
    h = (unsigned)(*(unsigned short*)&bh);
    l = (unsigned)(*(unsigned short*)&bl);
}
__device__ __forceinline__ void split4(float4 v, uint2& hh, uint2& ll) {
    unsigned h0,l0,h1,l1,h2,l2,h3,l3;
    split1(v.x,h0,l0); split1(v.y,h1,l1); split1(v.z,h2,l2); split1(v.w,h3,l3);
    hh.x = h0 | (h1<<16);  hh.y = h2 | (h3<<16);
    ll.x = l0 | (l1<<16);  ll.y = l2 | (l3<<16);
}
__device__ __forceinline__ void psplit2(float x, float y, uint32_t& h, uint32_t& l) {
    unsigned hx,lx,hy,ly;
    split1(x,hx,lx); split1(y,hy,ly);
    h = hx | (hy << 16);
    l = lx | (ly << 16);
}

__device__ __forceinline__ uint32_t smem_u32(const void* p) {
    uint32_t a;
    asm("{ .reg .u64 t; cvta.to.shared.u64 t, %1; cvt.u32.u64 %0, t; }"
        : "=r"(a) : "l"(p));
    return a;
}

// swizzles (unpadded, conflict-free ldmatrix)
__device__ __forceinline__ uint32_t sw64(uint32_t o)  { return o ^ ((o >> 3) & 0x30); }
__device__ __forceinline__ uint32_t sw128(uint32_t o) { return o ^ ((o >> 3) & 0x70); }

// cp.async helpers
__device__ __forceinline__ void cpa16(uint32_t s, const void* g) {
    asm volatile("cp.async.cg.shared.global [%0], [%1], 16;" :: "r"(s), "l"(g));
}
#define CP_COMMIT() asm volatile("cp.async.commit_group;" ::: "memory")
#define CP_WAIT1()  asm volatile("cp.async.wait_group 1;" ::: "memory")
#define CP_WAIT0()  asm volatile("cp.async.wait_group 0;" ::: "memory")

// ---------------------------------------------------------------------------
// split_x: X fp32 -> (g_xh, g_xl)
// ---------------------------------------------------------------------------
__global__ void __launch_bounds__(256) split_x(const float* __restrict__ X) {
    int i = blockIdx.x * 256 + threadIdx.x;
    float4 v = ((const float4*)X)[i];
    uint2 hh, ll;
    split4(v, hh, ll);
    ((uint2*)g_xh)[i] = hh;
    ((uint2*)g_xl)[i] = ll;
}

// ---------------------------------------------------------------------------
// split_bg: alpha * {Kbg,Vbg} fp32 -> bf16 splits at kv slots [1024, 2048)
// ---------------------------------------------------------------------------
__global__ void __launch_bounds__(256) split_bg(const float* __restrict__ Kbg,
                                                const float* __restrict__ Vbg) {
    const int z = blockIdx.y;
    const float* src = z ? Vbg : Kbg;
    __nv_bfloat16* dsth = z ? g_vh : g_kh;
    __nv_bfloat16* dstl = z ? g_vl : g_kl;
    size_t i = (size_t)blockIdx.x * 256 + threadIdx.x;
    float4 v = ((const float4*)src)[i];
    v.x *= ALPHA; v.y *= ALPHA; v.z *= ALPHA; v.w *= ALPHA;
    uint2 hh, ll;
    split4(v, hh, ll);
    size_t e = i * 4;
    size_t bh = e >> 16;
    size_t rem = e & 65535;
    size_t d = (bh << 17) + 65536 + rem;
    *(uint2*)&dsth[d] = hh;
    *(uint2*)&dstl[d] = ll;
}

// ---------------------------------------------------------------------------
// split_wT: W [k][n] fp32 -> W^T [n][k] bf16 hi/lo  (32x32 smem transpose)
// ---------------------------------------------------------------------------
__global__ void __launch_bounds__(256) split_wT(const float* __restrict__ Wq,
                                                const float* __restrict__ Wk,
                                                const float* __restrict__ Wv,
                                                const float* __restrict__ Wo) {
    const float* W = (blockIdx.z == 0) ? Wq : (blockIdx.z == 1) ? Wk
                   : (blockIdx.z == 2) ? Wv : Wo;
    __nv_bfloat16* dh = g_wth + (size_t)blockIdx.z * DD * DD;
    __nv_bfloat16* dl = g_wtl + (size_t)blockIdx.z * DD * DD;

    __shared__ float tile[32][33];
    const int t = threadIdx.x, tx = t & 31, ty = t >> 5;
    const int k0 = blockIdx.y * 32, n0 = blockIdx.x * 32;

    #pragma unroll
    for (int r = ty; r < 32; r += 8)
        tile[r][tx] = W[(size_t)(k0 + r) * DD + n0 + tx];
    __syncthreads();
    #pragma unroll
    for (int r = ty; r < 32; r += 8) {
        float v = tile[tx][r];
        unsigned h, l;
        split1(v, h, l);
        size_t idx = (size_t)(n0 + r) * DD + k0 + tx;
        dh[idx] = *(__nv_bfloat16*)&h;
        dl[idx] = *(__nv_bfloat16*)&l;
    }
}

// ---------------------------------------------------------------------------
// mma.sync primitives
// ---------------------------------------------------------------------------
__device__ __forceinline__ void ldmx4(uint32_t addr, uint32_t* r) {
    asm volatile("ldmatrix.sync.aligned.m8n8.x4.shared.b16 {%0,%1,%2,%3}, [%4];"
                 : "=r"(r[0]), "=r"(r[1]), "=r"(r[2]), "=r"(r[3]) : "r"(addr));
}
__device__ __forceinline__ void ldmx2(uint32_t addr, uint32_t* r) {
    asm volatile("ldmatrix.sync.aligned.m8n8.x2.shared.b16 {%0,%1}, [%2];"
                 : "=r"(r[0]), "=r"(r[1]) : "r"(addr));
}
__device__ __forceinline__ void ldmx2t(uint32_t addr, uint32_t* r) {
    asm volatile("ldmatrix.sync.aligned.m8n8.x2.trans.shared.b16 {%0,%1}, [%2];"
                 : "=r"(r[0]), "=r"(r[1]) : "r"(addr));
}
__device__ __forceinline__ void mma16816(float* c, const uint32_t* a, const uint32_t* b) {
    asm volatile(
        "mma.sync.aligned.m16n8k16.row.col.f32.bf16.bf16.f32 "
        "{%0,%1,%2,%3}, {%4,%5,%6,%7}, {%8,%9}, {%0,%1,%2,%3};"
        : "+f"(c[0]), "+f"(c[1]), "+f"(c[2]), "+f"(c[3])
        : "r"(a[0]), "r"(a[1]), "r"(a[2]), "r"(a[3]), "r"(b[0]), "r"(b[1]));
}

// ---------------------------------------------------------------------------
// GEMM core.  Block tile 128x128, K-chunk 32, 8 warps (2m x 4n), warp 64x32.
// 3-term split: AhBh + AhBl + AlBh.  Unpadded SW64 tiles.
// 3-stage cp.async ring, ONE __syncthreads per chunk (sync-then-prefetch).
// ---------------------------------------------------------------------------
#define KC2 32
#define SA_H 0
#define SA_L 8192
#define SB_H 16384
#define SB_L 24576
#define STG_GEMM 32768
#define SM_GEMM (3*STG_GEMM)
#define NCH (DD/KC2)

__device__ __forceinline__ void gemm_load_chunk(const __nv_bfloat16* __restrict__ Ah,
                                                const __nv_bfloat16* __restrict__ Al,
                                                const __nv_bfloat16* __restrict__ Bh,
                                                const __nv_bfloat16* __restrict__ Bl,
                                                uint32_t stg, int bm, int bn,
                                                int k0, int t) {
    #pragma unroll
    for (int i = 0; i < 8; i++) {
        int id = t + i * 256;            // 0..2047 chunks of 16 B
        int arr = id >> 9;               // 0:Ah 1:Al 2:Bh 3:Bl
        int idx = id & 511;
        int row = idx >> 2, c16 = idx & 3;
        const __nv_bfloat16* base =
            (arr == 0) ? Ah : (arr == 1) ? Al : (arr == 2) ? Bh : Bl;
        int rbase = (arr < 2) ? bm : bn;
        const __nv_bfloat16* src = base + (size_t)(rbase + row) * DD + k0 + c16 * 8;
        cpa16(stg + arr * 8192 + sw64(row * 64 + c16 * 16), src);
    }
}

__device__ __forceinline__ void mma_mainloop(const __nv_bfloat16* __restrict__ Ah,
                                             const __nv_bfloat16* __restrict__ Al,
                                             const __nv_bfloat16* __restrict__ Bh,
                                             const __nv_bfloat16* __restrict__ Bl,
                                             char* sm, int bm, int bn,
                                             float acc[4][4][4]) {
    const int t = threadIdx.x;
    const int wid = t >> 5, lane = t & 31;
    const int wm = (wid >> 2) * 64, wn = (wid & 3) * 32;
    const uint32_t smb = smem_u32(sm);

    const int a_r  = lane & 15;
    const int a_k8 = (lane >> 4) * 16;
    const int b_r  = lane & 7;
    const int b_k8 = ((lane >> 3) & 1) * 16;

    // prime stages 0 and 1
    gemm_load_chunk(Ah, Al, Bh, Bl, smb, bm, bn, 0, t);
    CP_COMMIT();
    gemm_load_chunk(Ah, Al, Bh, Bl, smb + STG_GEMM, bm, bn, KC2, t);
    CP_COMMIT();

    for (int c = 0; c < NCH; c++) {
        // ensure chunk c arrived (chunk c+1 may remain in flight)
        if (c + 1 < NCH) { CP_WAIT1(); } else { CP_WAIT0(); }
        __syncthreads();   // publishes chunk c; proves all warps done with chunk c-1
        if (c + 2 < NCH) {
            // stage (c+2)%3 was last read at iteration c-1 -> safe after the sync
            gemm_load_chunk(Ah, Al, Bh, Bl, smb + ((c + 2) % 3) * STG_GEMM,
                            bm, bn, (c + 2) * KC2, t);
            CP_COMMIT();
        }
        const uint32_t stg = smb + (c % 3) * STG_GEMM;

        #pragma unroll
        for (int ks = 0; ks < KC2; ks += 16) {
            uint32_t ah[4][4], al[4][4];
            #pragma unroll
            for (int mf = 0; mf < 4; mf++) {
                uint32_t ra = sw64((wm + mf * 16 + a_r) * 64 + ks * 2 + a_k8);
                ldmx4(stg + SA_H + ra, ah[mf]);
                ldmx4(stg + SA_L + ra, al[mf]);
            }
            #pragma unroll
            for (int nf = 0; nf < 4; nf++) {
                uint32_t bh[2], bl[2];
                uint32_t rb = sw64((wn + nf * 8 + b_r) * 64 + ks * 2 + b_k8);
                ldmx2(stg + SB_H + rb, bh);
                ldmx2(stg + SB_L + rb, bl);
                #pragma unroll
                for (int mf = 0; mf < 4; mf++) {
                    mma16816(acc[mf][nf], ah[mf], bh);
                    mma16816(acc[mf][nf], ah[mf], bl);
                    mma16816(acc[mf][nf], al[mf], bh);
                }
            }
        }
    }
    __syncthreads();   // protect smem before epilogue reuse / exit
}

// QKV GEMM: epilogue splits directly to bf16 hi/lo in attention layout.
__global__ void __launch_bounds__(256, 2) mma_qkv() {
    extern __shared__ char smd[];
    const int t = threadIdx.x, wid = t >> 5, lane = t & 31;
    const int wm = (wid >> 2) * 64, wn = (wid & 3) * 32;
    const int bm = blockIdx.y * 128, bn = blockIdx.x * 128;
    const int z = blockIdx.z;

    const __nv_bfloat16* Bh = g_wth + (size_t)z * DD * DD;
    const __nv_bfloat16* Bl = g_wtl + (size_t)z * DD * DD;
    __nv_bfloat16* dh_ = (z == 0) ? g_qh : (z == 1) ? g_kh : g_vh;
    __nv_bfloat16* dl_ = (z == 0) ? g_ql : (z == 1) ? g_kl : g_vl;
    const float mul = (z == 0) ? SCALE : 1.0f;
    const int shift = (z == 0) ? 16 : 17;

    float acc[4][4][4] = {};
    mma_mainloop(g_xh, g_xl, Bh, Bl, smd, bm, bn, acc);

    const int gid = lane >> 2, tig = lane & 3;
    #pragma unroll
    for (int mf = 0; mf < 4; mf++) {
        #pragma unroll
        for (int nf = 0; nf < 4; nf++) {
            int n = bn + wn + nf * 8 + tig * 2;
            int hh = n >> 6, dh = n & 63;
            #pragma unroll
            for (int half = 0; half < 2; half++) {
                int m = bm + wm + mf * 16 + gid + half * 8;
                int bb = m >> 10, lq2 = m & 1023;
                int bhh = bb * HH + hh;
                size_t idx = ((size_t)bhh << shift) + ((size_t)lq2 << 6) + dh;
                uint32_t hv, lv;
                psplit2(acc[mf][nf][half*2] * mul, acc[mf][nf][half*2+1] * mul, hv, lv);
                *(uint32_t*)&dh_[idx] = hv;
                *(uint32_t*)&dl_[idx] = lv;
            }
        }
    }
}

// Output GEMM: ctx (bf16 split) @ Wo^T + bias -> out
__global__ void __launch_bounds__(256, 2) mma_out(const float* __restrict__ bo,
                                                  float* __restrict__ out) {
    extern __shared__ char smd[];
    const int t = threadIdx.x, wid = t >> 5, lane = t & 31;
    const int wm = (wid >> 2) * 64, wn = (wid & 3) * 32;
    const int bm = blockIdx.y * 128, bn = blockIdx.x * 128;

    const __nv_bfloat16* Bh = g_wth + (size_t)3 * DD * DD;
    const __nv_bfloat16* Bl = g_wtl + (size_t)3 * DD * DD;

    float acc[4][4][4] = {};
    mma_mainloop(g_ctxh, g_ctxl, Bh, Bl, smd, bm, bn, acc);

    const int gid = lane >> 2, tig = lane & 3;
    #pragma unroll
    for (int mf = 0; mf < 4; mf++) {
        #pragma unroll
        for (int nf = 0; nf < 4; nf++) {
            int m = bm + wm + mf * 16 + gid;
            int n = bn + wn + nf * 8 + tig * 2;
            float2 bv = *(const float2*)(bo + n);
            *(float2*)(out + (size_t)m * DD + n) =
                make_float2(acc[mf][nf][0] + bv.x, acc[mf][nf][1] + bv.y);
            *(float2*)(out + (size_t)(m + 8) * DD + n) =
                make_float2(acc[mf][nf][2] + bv.x, acc[mf][nf][3] + bv.y);
        }
    }
}

// ---------------------------------------------------------------------------
// Tensor-core flash attention, 256 threads (8 warps), 128-q-row tile.
// Unpadded SW128 tiles, cp.async 2-stage KV ring, ONE sync per kv tile.
// ---------------------------------------------------------------------------
#define AQH 0
#define AQL 16384
#define AKV 32768           // stages: Kh +0, Kl +8192, Vh +16384, Vl +24576
#define STG_KV 32768
#define SM_ATTN (AKV + 2*STG_KV)   // 98304

__device__ __forceinline__ void attn_load_kv(uint32_t stg, size_t src0, int t) {
    #pragma unroll
    for (int i = 0; i < 8; i++) {
        int id = t + i * 256;        // 0..2047
        int arr = id >> 9;           // 0:Kh 1:Kl 2:Vh 3:Vl
        int idx = id & 511;
        int row = idx >> 3, c16 = idx & 7;
        const __nv_bfloat16* s =
            ((arr == 0) ? g_kh : (arr == 1) ? g_kl : (arr == 2) ? g_vh : g_vl)
            + src0 + row * 64 + c16 * 8;
        cpa16(stg + arr * 8192 + sw128(row * 128 + c16 * 16), s);
    }
}

__global__ void __launch_bounds__(256, 2) attn_mma() {
    extern __shared__ char sm[];
    const uint32_t smb = smem_u32(sm);
    const int t = threadIdx.x, wid = t >> 5, lane = t & 31;
    const int gid = lane >> 2, tig = lane & 3;
    const int bh = blockIdx.y, q0 = blockIdx.x << 7;
    const int bb = bh / HH, hh = bh % HH;

    const size_t kvbase = (size_t)bh << 17;   // bh * 2048 * 64

    // prefetch KV tile 0 (stage 0)
    attn_load_kv(smb + AKV, kvbase, t);
    CP_COMMIT();

    // ---- load Q tile (128 rows x 64 bf16, hi+lo), SW128
    {
        const __nv_bfloat16* qh = g_qh + ((size_t)bh << 16) + ((size_t)q0 << 6);
        const __nv_bfloat16* ql = g_ql + ((size_t)bh << 16) + ((size_t)q0 << 6);
        #pragma unroll
        for (int i = 0; i < 8; i++) {
            int id = t + i * 256;        // 0..2047
            int sel = id >> 10;
            int idx = id & 1023;
            int row = idx >> 3, c16 = idx & 7;
            const __nv_bfloat16* src = (sel ? ql : qh) + row * 64 + c16 * 8;
            uint4 v = *(const uint4*)src;
            *(uint4*)(sm + (sel ? AQL : AQH) + sw128(row * 128 + c16 * 16)) = v;
        }
    }

    float oacc[8][4] = {};
    float mrow[2] = {-1e30f, -1e30f};
    float lrow[2] = {0.0f, 0.0f};

    const int a_r  = lane & 15;
    const int a_k16 = (lane >> 4) * 16;
    const int b_r  = lane & 7;
    const int b_k16 = ((lane >> 3) & 1) * 16;
    const int v_r  = (lane & 7) + ((lane >> 3) & 1) * 8;

    for (int tile = 0; tile < 32; tile++) {
        CP_WAIT0();
        __syncthreads();   // publish tile's KV (and Q on iter 0); prove stage free
        if (tile + 1 < 32) {
            // stage (tile+1)&1 was last read at iteration tile-1 -> safe
            attn_load_kv(smb + AKV + ((tile + 1) & 1) * STG_KV,
                         kvbase + ((size_t)((tile + 1) << 6) << 6), t);
            CP_COMMIT();
        }
        const uint32_t kstg = smb + AKV + (tile & 1) * STG_KV;
        const uint32_t vstg = kstg + 16384;

        // ---- S = Q K^T
        float sacc[8][4] = {};
        #pragma unroll
        for (int ks = 0; ks < 4; ks++) {
            uint32_t ah[4], al[4];
            uint32_t ra = sw128((wid * 16 + a_r) * 128 + ks * 32 + a_k16);
            ldmx4(smb + AQH + ra, ah);
            ldmx4(smb + AQL + ra, al);
            #pragma unroll
            for (int nf = 0; nf < 8; nf++) {
                uint32_t kh2[2], kl2[2];
                uint32_t rb = sw128((nf * 8 + b_r) * 128 + ks * 32 + b_k16);
                ldmx2(kstg + rb, kh2);
                ldmx2(kstg + 8192 + rb, kl2);
                mma16816(sacc[nf], ah, kh2);
                mma16816(sacc[nf], ah, kl2);
                mma16816(sacc[nf], al, kh2);
            }
        }

        // ---- online softmax (rows gid, gid+8 within warp's 16 rows)
        #pragma unroll
        for (int rr = 0; rr < 2; rr++) {
            const int o0 = rr * 2;
            float mx = -1e30f;
            #pragma unroll
            for (int nf = 0; nf < 8; nf++)
                mx = fmaxf(mx, fmaxf(sacc[nf][o0], sacc[nf][o0 + 1]));
            mx = fmaxf(mx, __shfl_xor_sync(0xffffffffu, mx, 1));
            mx = fmaxf(mx, __shfl_xor_sync(0xffffffffu, mx, 2));
            float mn = fmaxf(mrow[rr], mx);
            float corr = __expf(mrow[rr] - mn);
            mrow[rr] = mn;
            float rs = 0.0f;
            #pragma unroll
            for (int nf = 0; nf < 8; nf++) {
                float p0 = __expf(sacc[nf][o0] - mn);
                float p1 = __expf(sacc[nf][o0 + 1] - mn);
                sacc[nf][o0] = p0; sacc[nf][o0 + 1] = p1;
                rs += p0 + p1;
            }
            rs += __shfl_xor_sync(0xffffffffu, rs, 1);
            rs += __shfl_xor_sync(0xffffffffu, rs, 2);
            lrow[rr] = lrow[rr] * corr + rs;
            #pragma unroll
            for (int nf = 0; nf < 8; nf++) {
                oacc[nf][o0]     *= corr;
                oacc[nf][o0 + 1] *= corr;
            }
        }

        // ---- O += P V
        #pragma unroll
        for (int ks = 0; ks < 4; ks++) {
            const float* f0 = sacc[2 * ks];
            const float* f1 = sacc[2 * ks + 1];
            uint32_t ph[4], pl[4];
            psplit2(f0[0], f0[1], ph[0], pl[0]);
            psplit2(f0[2], f0[3], ph[1], pl[1]);
            psplit2(f1[0], f1[1], ph[2], pl[2]);
            psplit2(f1[2], f1[3], ph[3], pl[3]);
            #pragma unroll
            for (int nf = 0; nf < 8; nf++) {
                uint32_t vh2[2], vl2[2];
                uint32_t rv = sw128((ks * 16 + v_r) * 128 + nf * 16);
                ldmx2t(vstg + rv, vh2);
                ldmx2t(vstg + 8192 + rv, vl2);
                mma16816(oacc[nf], ph, vh2);
                mma16816(oacc[nf], ph, vl2);
                mma16816(oacc[nf], pl, vh2);
            }
        }
    }

    // ---- epilogue: normalize, split, write ctx [B, L, D]
    const float inv0 = 1.0f / lrow[0];
    const float inv1 = 1.0f / lrow[1];
    const int lq0 = q0 + wid * 16 + gid;
    const size_t base0 = ((size_t)(bb * LQ + lq0)) * DD + hh * 64;
    const size_t base1 = ((size_t)(bb * LQ + lq0 + 8)) * DD + hh * 64;
    #pragma unroll
    for (int nf = 0; nf < 8; nf++) {
        const int col = nf * 8 + tig * 2;
        uint32_t hv, lv;
        psplit2(oacc[nf][0] * inv0, oacc[nf][1] * inv0, hv, lv);
        *(uint32_t*)&g_ctxh[base0 + col] = hv;
        *(uint32_t*)&g_ctxl[base0 + col] = lv;
        psplit2(oacc[nf][2] * inv1, oacc[nf][3] * inv1, hv, lv);
        *(uint32_t*)&g_ctxh[base1 + col] = hv;
        *(uint32_t*)&g_ctxl[base1 + col] = lv;
    }
}

// ---------------------------------------------------------------------------

extern "C" void kernel_launch(void* const* d_in, const int* in_sizes, int n_in,
                              void* d_out, int out_size) {
    const float* X   = (const float*)d_in[0];
    const float* Wq  = (const float*)d_in[1];
    const float* Wk  = (const float*)d_in[2];
    const float* Wv  = (const float*)d_in[3];
    const float* Wo  = (const float*)d_in[4];
    const float* bo  = (const float*)d_in[5];
    const float* Kbg = (const float*)d_in[6];
    const float* Vbg = (const float*)d_in[7];
    float* out = (float*)d_out;

    cudaFuncSetAttribute(mma_qkv, cudaFuncAttributeMaxDynamicSharedMemorySize, SM_GEMM);
    cudaFuncSetAttribute(mma_out, cudaFuncAttributeMaxDynamicSharedMemorySize, SM_GEMM);
    cudaFuncSetAttribute(attn_mma, cudaFuncAttributeMaxDynamicSharedMemorySize, SM_ATTN);

    split_x<<<MTOT * DD / 4 / 256, 256>>>(X);
    split_wT<<<dim3(DD / 32, DD / 32, 4), 256>>>(Wq, Wk, Wv, Wo);
    split_bg<<<dim3(BH * LQ * DHD / 4 / 256, 2), 256>>>(Kbg, Vbg);

    mma_qkv<<<dim3(DD / 128, MTOT / 128, 3), 256, SM_GEMM>>>();

    attn_mma<<<dim3(LQ / 128, BH), 256, SM_ATTN>>>();

    mma_out<<<dim3(DD / 128, MTOT / 128), 256, SM_GEMM>>>(bo, out);
}

// round 16
// speedup vs baseline: 3.1925x; 1.0534x over previous
#include <cuda_runtime.h>
#include <cuda_bf16.h>
#include <cstdint>

#define BQ 4
#define LQ 1024
#define DD 1280
#define HH 20
#define DHD 64
#define BH (BQ*HH)          // 80
#define MTOT (BQ*LQ)        // 4096
#define KV2 2048
#define ALPHA 0.48f
#define SCALE 0.125f        // 1/sqrt(64)

// ---------------------------------------------------------------------------
// Static device scratch (allocation-free)
// ---------------------------------------------------------------------------
__device__ __nv_bfloat16 g_xh[MTOT*DD],  g_xl[MTOT*DD];        // X  [m][k]
__device__ __nv_bfloat16 g_ctxh[MTOT*DD], g_ctxl[MTOT*DD];     // ctx [m][k]
__device__ __nv_bfloat16 g_wth[4*DD*DD], g_wtl[4*DD*DD];       // W^T [n][k]
__device__ __nv_bfloat16 g_qh[BH*LQ*DHD],  g_ql[BH*LQ*DHD];    // Q*SCALE split
__device__ __nv_bfloat16 g_kh[BH*KV2*DHD], g_kl[BH*KV2*DHD];   // K (self+bg)
__device__ __nv_bfloat16 g_vh[BH*KV2*DHD], g_vl[BH*KV2*DHD];   // V (self+bg)

// ---------------------------------------------------------------------------
// Split helpers: x = hi + lo, both bf16
// ---------------------------------------------------------------------------
__device__ __forceinline__ void split1(float x, unsigned& h, unsigned& l) {
    __nv_bfloat16 bh = __float2bfloat16_rn(x);
    float r = x - __bfloat162float(bh);
    __nv_bfloat16 bl = __float2bfloat16_rn(r);
    h = (unsigned)(*(unsigned short*)&bh);
    l = (unsigned)(*(unsigned short*)&bl);
}
__device__ __forceinline__ void split4(float4 v, uint2& hh, uint2& ll) {
    unsigned h0,l0,h1,l1,h2,l2,h3,l3;
    split1(v.x,h0,l0); split1(v.y,h1,l1); split1(v.z,h2,l2); split1(v.w,h3,l3);
    hh.x = h0 | (h1<<16);  hh.y = h2 | (h3<<16);
    ll.x = l0 | (l1<<16);  ll.y = l2 | (l3<<16);
}
__device__ __forceinline__ void psplit2(float x, float y, uint32_t& h, uint32_t& l) {
    unsigned hx,lx,hy,ly;
    split1(x,hx,lx); split1(y,hy,ly);
    h = hx | (hy << 16);
    l = lx | (ly << 16);
}

__device__ __forceinline__ uint32_t smem_u32(const void* p) {
    uint32_t a;
    asm("{ .reg .u64 t; cvta.to.shared.u64 t, %1; cvt.u32.u64 %0, t; }"
        : "=r"(a) : "l"(p));
    return a;
}

// swizzles (unpadded, conflict-free ldmatrix)
__device__ __forceinline__ uint32_t sw64(uint32_t o)  { return o ^ ((o >> 3) & 0x30); }
__device__ __forceinline__ uint32_t sw128(uint32_t o) { return o ^ ((o >> 3) & 0x70); }

// cp.async helpers
__device__ __forceinline__ void cpa16(uint32_t s, const void* g) {
    asm volatile("cp.async.cg.shared.global [%0], [%1], 16;" :: "r"(s), "l"(g));
}
#define CP_COMMIT() asm volatile("cp.async.commit_group;" ::: "memory")
#define CP_WAIT1()  asm volatile("cp.async.wait_group 1;" ::: "memory")
#define CP_WAIT0()  asm volatile("cp.async.wait_group 0;" ::: "memory")

// ---------------------------------------------------------------------------
// split_x: X fp32 -> (g_xh, g_xl)
// ---------------------------------------------------------------------------
__global__ void __launch_bounds__(256) split_x(const float* __restrict__ X) {
    int i = blockIdx.x * 256 + threadIdx.x;
    float4 v = ((const float4*)X)[i];
    uint2 hh, ll;
    split4(v, hh, ll);
    ((uint2*)g_xh)[i] = hh;
    ((uint2*)g_xl)[i] = ll;
}

// ---------------------------------------------------------------------------
// split_bg: alpha * {Kbg,Vbg} fp32 -> bf16 splits at kv slots [1024, 2048)
// ---------------------------------------------------------------------------
__global__ void __launch_bounds__(256) split_bg(const float* __restrict__ Kbg,
                                                const float* __restrict__ Vbg) {
    const int z = blockIdx.y;
    const float* src = z ? Vbg : Kbg;
    __nv_bfloat16* dsth = z ? g_vh : g_kh;
    __nv_bfloat16* dstl = z ? g_vl : g_kl;
    size_t i = (size_t)blockIdx.x * 256 + threadIdx.x;
    float4 v = ((const float4*)src)[i];
    v.x *= ALPHA; v.y *= ALPHA; v.z *= ALPHA; v.w *= ALPHA;
    uint2 hh, ll;
    split4(v, hh, ll);
    size_t e = i * 4;
    size_t bh = e >> 16;
    size_t rem = e & 65535;
    size_t d = (bh << 17) + 65536 + rem;
    *(uint2*)&dsth[d] = hh;
    *(uint2*)&dstl[d] = ll;
}

// ---------------------------------------------------------------------------
// split_wT: W [k][n] fp32 -> W^T [n][k] bf16 hi/lo  (32x32 smem transpose)
// ---------------------------------------------------------------------------
__global__ void __launch_bounds__(256) split_wT(const float* __restrict__ Wq,
                                                const float* __restrict__ Wk,
                                                const float* __restrict__ Wv,
                                                const float* __restrict__ Wo) {
    const float* W = (blockIdx.z == 0) ? Wq : (blockIdx.z == 1) ? Wk
                   : (blockIdx.z == 2) ? Wv : Wo;
    __nv_bfloat16* dh = g_wth + (size_t)blockIdx.z * DD * DD;
    __nv_bfloat16* dl = g_wtl + (size_t)blockIdx.z * DD * DD;

    __shared__ float tile[32][33];
    const int t = threadIdx.x, tx = t & 31, ty = t >> 5;
    const int k0 = blockIdx.y * 32, n0 = blockIdx.x * 32;

    #pragma unroll
    for (int r = ty; r < 32; r += 8)
        tile[r][tx] = W[(size_t)(k0 + r) * DD + n0 + tx];
    __syncthreads();
    #pragma unroll
    for (int r = ty; r < 32; r += 8) {
        float v = tile[tx][r];
        unsigned h, l;
        split1(v, h, l);
        size_t idx = (size_t)(n0 + r) * DD + k0 + tx;
        dh[idx] = *(__nv_bfloat16*)&h;
        dl[idx] = *(__nv_bfloat16*)&l;
    }
}

// ---------------------------------------------------------------------------
// mma.sync primitives
// ---------------------------------------------------------------------------
__device__ __forceinline__ void ldmx4(uint32_t addr, uint32_t* r) {
    asm volatile("ldmatrix.sync.aligned.m8n8.x4.shared.b16 {%0,%1,%2,%3}, [%4];"
                 : "=r"(r[0]), "=r"(r[1]), "=r"(r[2]), "=r"(r[3]) : "r"(addr));
}
__device__ __forceinline__ void ldmx4t(uint32_t addr, uint32_t* r) {
    asm volatile("ldmatrix.sync.aligned.m8n8.x4.trans.shared.b16 {%0,%1,%2,%3}, [%4];"
                 : "=r"(r[0]), "=r"(r[1]), "=r"(r[2]), "=r"(r[3]) : "r"(addr));
}
__device__ __forceinline__ void mma16816(float* c, const uint32_t* a, const uint32_t* b) {
    asm volatile(
        "mma.sync.aligned.m16n8k16.row.col.f32.bf16.bf16.f32 "
        "{%0,%1,%2,%3}, {%4,%5,%6,%7}, {%8,%9}, {%0,%1,%2,%3};"
        : "+f"(c[0]), "+f"(c[1]), "+f"(c[2]), "+f"(c[3])
        : "r"(a[0]), "r"(a[1]), "r"(a[2]), "r"(a[3]), "r"(b[0]), "r"(b[1]));
}

// ---------------------------------------------------------------------------
// GEMM core.  Block tile 128x128, K-chunk 32, 8 warps (2m x 4n), warp 64x32.
// 3-term split: AhBh + AhBl + AlBh.  Unpadded SW64 tiles.
// 3-stage cp.async ring, ONE __syncthreads per chunk.
// B fragments loaded pairwise via ldmatrix.x4 (2 n8-frags per instruction).
// ---------------------------------------------------------------------------
#define KC2 32
#define SA_H 0
#define SA_L 8192
#define SB_H 16384
#define SB_L 24576
#define STG_GEMM 32768
#define SM_GEMM (3*STG_GEMM)
#define NCH (DD/KC2)

__device__ __forceinline__ void gemm_load_chunk(const __nv_bfloat16* __restrict__ Ah,
                                                const __nv_bfloat16* __restrict__ Al,
                                                const __nv_bfloat16* __restrict__ Bh,
                                                const __nv_bfloat16* __restrict__ Bl,
                                                uint32_t stg, int bm, int bn,
                                                int k0, int t) {
    #pragma unroll
    for (int i = 0; i < 8; i++) {
        int id = t + i * 256;            // 0..2047 chunks of 16 B
        int arr = id >> 9;               // 0:Ah 1:Al 2:Bh 3:Bl
        int idx = id & 511;
        int row = idx >> 2, c16 = idx & 3;
        const __nv_bfloat16* base =
            (arr == 0) ? Ah : (arr == 1) ? Al : (arr == 2) ? Bh : Bl;
        int rbase = (arr < 2) ? bm : bn;
        const __nv_bfloat16* src = base + (size_t)(rbase + row) * DD + k0 + c16 * 8;
        cpa16(stg + arr * 8192 + sw64(row * 64 + c16 * 16), src);
    }
}

__device__ __forceinline__ void mma_mainloop(const __nv_bfloat16* __restrict__ Ah,
                                             const __nv_bfloat16* __restrict__ Al,
                                             const __nv_bfloat16* __restrict__ Bh,
                                             const __nv_bfloat16* __restrict__ Bl,
                                             char* sm, int bm, int bn,
                                             float acc[4][4][4]) {
    const int t = threadIdx.x;
    const int wid = t >> 5, lane = t & 31;
    const int wm = (wid >> 2) * 64, wn = (wid & 3) * 32;
    const uint32_t smb = smem_u32(sm);

    const int a_r  = lane & 15;
    const int a_k8 = (lane >> 4) * 16;
    // x4 B-pair addressing: lane groups -> {nf0 k0, nf0 k8, nf1 k0, nf1 k8}
    const int b4_r = (lane & 7) + ((lane >> 4) & 1) * 8;   // n row within 16
    const int b4_k = ((lane >> 3) & 1) * 16;               // k-half byte offset

    // prime stages 0 and 1
    gemm_load_chunk(Ah, Al, Bh, Bl, smb, bm, bn, 0, t);
    CP_COMMIT();
    gemm_load_chunk(Ah, Al, Bh, Bl, smb + STG_GEMM, bm, bn, KC2, t);
    CP_COMMIT();

    for (int c = 0; c < NCH; c++) {
        if (c + 1 < NCH) { CP_WAIT1(); } else { CP_WAIT0(); }
        __syncthreads();
        if (c + 2 < NCH) {
            gemm_load_chunk(Ah, Al, Bh, Bl, smb + ((c + 2) % 3) * STG_GEMM,
                            bm, bn, (c + 2) * KC2, t);
            CP_COMMIT();
        }
        const uint32_t stg = smb + (c % 3) * STG_GEMM;

        #pragma unroll
        for (int ks = 0; ks < KC2; ks += 16) {
            uint32_t ah[4][4], al[4][4];
            #pragma unroll
            for (int mf = 0; mf < 4; mf++) {
                uint32_t ra = sw64((wm + mf * 16 + a_r) * 64 + ks * 2 + a_k8);
                ldmx4(stg + SA_H + ra, ah[mf]);
                ldmx4(stg + SA_L + ra, al[mf]);
            }
            #pragma unroll
            for (int nfp = 0; nfp < 2; nfp++) {
                uint32_t bh4[4], bl4[4];
                uint32_t rb = sw64((wn + nfp * 16 + b4_r) * 64 + ks * 2 + b4_k);
                ldmx4(stg + SB_H + rb, bh4);
                ldmx4(stg + SB_L + rb, bl4);
                #pragma unroll
                for (int sub = 0; sub < 2; sub++) {
                    const int nf = nfp * 2 + sub;
                    const uint32_t* bh = bh4 + sub * 2;
                    const uint32_t* bl = bl4 + sub * 2;
                    #pragma unroll
                    for (int mf = 0; mf < 4; mf++) {
                        mma16816(acc[mf][nf], ah[mf], bh);
                        mma16816(acc[mf][nf], ah[mf], bl);
                        mma16816(acc[mf][nf], al[mf], bh);
                    }
                }
            }
        }
    }
    __syncthreads();
}

// QKV GEMM: epilogue splits directly to bf16 hi/lo in attention layout.
__global__ void __launch_bounds__(256, 2) mma_qkv() {
    extern __shared__ char smd[];
    const int t = threadIdx.x, wid = t >> 5, lane = t & 31;
    const int wm = (wid >> 2) * 64, wn = (wid & 3) * 32;
    const int bm = blockIdx.y * 128, bn = blockIdx.x * 128;
    const int z = blockIdx.z;

    const __nv_bfloat16* Bh = g_wth + (size_t)z * DD * DD;
    const __nv_bfloat16* Bl = g_wtl + (size_t)z * DD * DD;
    __nv_bfloat16* dh_ = (z == 0) ? g_qh : (z == 1) ? g_kh : g_vh;
    __nv_bfloat16* dl_ = (z == 0) ? g_ql : (z == 1) ? g_kl : g_vl;
    const float mul = (z == 0) ? SCALE : 1.0f;
    const int shift = (z == 0) ? 16 : 17;

    float acc[4][4][4] = {};
    mma_mainloop(g_xh, g_xl, Bh, Bl, smd, bm, bn, acc);

    const int gid = lane >> 2, tig = lane & 3;
    #pragma unroll
    for (int mf = 0; mf < 4; mf++) {
        #pragma unroll
        for (int nf = 0; nf < 4; nf++) {
            int n = bn + wn + nf * 8 + tig * 2;
            int hh = n >> 6, dh = n & 63;
            #pragma unroll
            for (int half = 0; half < 2; half++) {
                int m = bm + wm + mf * 16 + gid + half * 8;
                int bb = m >> 10, lq2 = m & 1023;
                int bhh = bb * HH + hh;
                size_t idx = ((size_t)bhh << shift) + ((size_t)lq2 << 6) + dh;
                uint32_t hv, lv;
                psplit2(acc[mf][nf][half*2] * mul, acc[mf][nf][half*2+1] * mul, hv, lv);
                *(uint32_t*)&dh_[idx] = hv;
                *(uint32_t*)&dl_[idx] = lv;
            }
        }
    }
}

// Output GEMM: ctx (bf16 split) @ Wo^T + bias -> out
__global__ void __launch_bounds__(256, 2) mma_out(const float* __restrict__ bo,
                                                  float* __restrict__ out) {
    extern __shared__ char smd[];
    const int t = threadIdx.x, wid = t >> 5, lane = t & 31;
    const int wm = (wid >> 2) * 64, wn = (wid & 3) * 32;
    const int bm = blockIdx.y * 128, bn = blockIdx.x * 128;

    const __nv_bfloat16* Bh = g_wth + (size_t)3 * DD * DD;
    const __nv_bfloat16* Bl = g_wtl + (size_t)3 * DD * DD;

    float acc[4][4][4] = {};
    mma_mainloop(g_ctxh, g_ctxl, Bh, Bl, smd, bm, bn, acc);

    const int gid = lane >> 2, tig = lane & 3;
    #pragma unroll
    for (int mf = 0; mf < 4; mf++) {
        #pragma unroll
        for (int nf = 0; nf < 4; nf++) {
            int m = bm + wm + mf * 16 + gid;
            int n = bn + wn + nf * 8 + tig * 2;
            float2 bv = *(const float2*)(bo + n);
            *(float2*)(out + (size_t)m * DD + n) =
                make_float2(acc[mf][nf][0] + bv.x, acc[mf][nf][1] + bv.y);
            *(float2*)(out + (size_t)(m + 8) * DD + n) =
                make_float2(acc[mf][nf][2] + bv.x, acc[mf][nf][3] + bv.y);
        }
    }
}

// ---------------------------------------------------------------------------
// Tensor-core flash attention, 256 threads (8 warps), 128-q-row tile.
// Unpadded SW128 tiles, cp.async 2-stage KV ring, ONE sync per kv tile.
// K and V fragments loaded pairwise via ldmatrix.x4 / x4.trans.
// ---------------------------------------------------------------------------
#define AQH 0
#define AQL 16384
#define AKV 32768           // stages: Kh +0, Kl +8192, Vh +16384, Vl +24576
#define STG_KV 32768
#define SM_ATTN (AKV + 2*STG_KV)   // 98304

__device__ __forceinline__ void attn_load_kv(uint32_t stg, size_t src0, int t) {
    #pragma unroll
    for (int i = 0; i < 8; i++) {
        int id = t + i * 256;        // 0..2047
        int arr = id >> 9;           // 0:Kh 1:Kl 2:Vh 3:Vl
        int idx = id & 511;
        int row = idx >> 3, c16 = idx & 7;
        const __nv_bfloat16* s =
            ((arr == 0) ? g_kh : (arr == 1) ? g_kl : (arr == 2) ? g_vh : g_vl)
            + src0 + row * 64 + c16 * 8;
        cpa16(stg + arr * 8192 + sw128(row * 128 + c16 * 16), s);
    }
}

__global__ void __launch_bounds__(256, 2) attn_mma() {
    extern __shared__ char sm[];
    const uint32_t smb = smem_u32(sm);
    const int t = threadIdx.x, wid = t >> 5, lane = t & 31;
    const int gid = lane >> 2, tig = lane & 3;
    const int bh = blockIdx.y, q0 = blockIdx.x << 7;
    const int bb = bh / HH, hh = bh % HH;

    const size_t kvbase = (size_t)bh << 17;   // bh * 2048 * 64

    // prefetch KV tile 0 (stage 0)
    attn_load_kv(smb + AKV, kvbase, t);
    CP_COMMIT();

    // ---- load Q tile (128 rows x 64 bf16, hi+lo), SW128
    {
        const __nv_bfloat16* qh = g_qh + ((size_t)bh << 16) + ((size_t)q0 << 6);
        const __nv_bfloat16* ql = g_ql + ((size_t)bh << 16) + ((size_t)q0 << 6);
        #pragma unroll
        for (int i = 0; i < 8; i++) {
            int id = t + i * 256;        // 0..2047
            int sel = id >> 10;
            int idx = id & 1023;
            int row = idx >> 3, c16 = idx & 7;
            const __nv_bfloat16* src = (sel ? ql : qh) + row * 64 + c16 * 8;
            uint4 v = *(const uint4*)src;
            *(uint4*)(sm + (sel ? AQL : AQH) + sw128(row * 128 + c16 * 16)) = v;
        }
    }

    float oacc[8][4] = {};
    float mrow[2] = {-1e30f, -1e30f};
    float lrow[2] = {0.0f, 0.0f};

    const int a_r  = lane & 15;
    const int a_k16 = (lane >> 4) * 16;
    // K x4 pair addressing: {nf0 k0, nf0 k8, nf1 k0, nf1 k8}
    const int k4_r = (lane & 7) + ((lane >> 4) & 1) * 8;
    const int k4_k = ((lane >> 3) & 1) * 16;
    // V x4.trans pair addressing: {nf0 k0-7, nf0 k8-15, nf1 k0-7, nf1 k8-15}
    const int v4_r = (lane & 7) + ((lane >> 3) & 1) * 8;   // kv row within 16
    const int v4_n = ((lane >> 4) & 1) * 16;               // second-nf byte offset

    for (int tile = 0; tile < 32; tile++) {
        CP_WAIT0();
        __syncthreads();
        if (tile + 1 < 32) {
            attn_load_kv(smb + AKV + ((tile + 1) & 1) * STG_KV,
                         kvbase + ((size_t)((tile + 1) << 6) << 6), t);
            CP_COMMIT();
        }
        const uint32_t kstg = smb + AKV + (tile & 1) * STG_KV;
        const uint32_t vstg = kstg + 16384;

        // ---- S = Q K^T
        float sacc[8][4] = {};
        #pragma unroll
        for (int ks = 0; ks < 4; ks++) {
            uint32_t ah[4], al[4];
            uint32_t ra = sw128((wid * 16 + a_r) * 128 + ks * 32 + a_k16);
            ldmx4(smb + AQH + ra, ah);
            ldmx4(smb + AQL + ra, al);
            #pragma unroll
            for (int nfp = 0; nfp < 4; nfp++) {
                uint32_t kh4[4], kl4[4];
                uint32_t rb = sw128((nfp * 16 + k4_r) * 128 + ks * 32 + k4_k);
                ldmx4(kstg + rb, kh4);
                ldmx4(kstg + 8192 + rb, kl4);
                #pragma unroll
                for (int sub = 0; sub < 2; sub++) {
                    const int nf = nfp * 2 + sub;
                    mma16816(sacc[nf], ah, kh4 + sub * 2);
                    mma16816(sacc[nf], ah, kl4 + sub * 2);
                    mma16816(sacc[nf], al, kh4 + sub * 2);
                }
            }
        }

        // ---- online softmax (rows gid, gid+8 within warp's 16 rows)
        #pragma unroll
        for (int rr = 0; rr < 2; rr++) {
            const int o0 = rr * 2;
            float mx = -1e30f;
            #pragma unroll
            for (int nf = 0; nf < 8; nf++)
                mx = fmaxf(mx, fmaxf(sacc[nf][o0], sacc[nf][o0 + 1]));
            mx = fmaxf(mx, __shfl_xor_sync(0xffffffffu, mx, 1));
            mx = fmaxf(mx, __shfl_xor_sync(0xffffffffu, mx, 2));
            float mn = fmaxf(mrow[rr], mx);
            float corr = __expf(mrow[rr] - mn);
            mrow[rr] = mn;
            float rs = 0.0f;
            #pragma unroll
            for (int nf = 0; nf < 8; nf++) {
                float p0 = __expf(sacc[nf][o0] - mn);
                float p1 = __expf(sacc[nf][o0 + 1] - mn);
                sacc[nf][o0] = p0; sacc[nf][o0 + 1] = p1;
                rs += p0 + p1;
            }
            rs += __shfl_xor_sync(0xffffffffu, rs, 1);
            rs += __shfl_xor_sync(0xffffffffu, rs, 2);
            lrow[rr] = lrow[rr] * corr + rs;
            #pragma unroll
            for (int nf = 0; nf < 8; nf++) {
                oacc[nf][o0]     *= corr;
                oacc[nf][o0 + 1] *= corr;
            }
        }

        // ---- O += P V
        #pragma unroll
        for (int ks = 0; ks < 4; ks++) {
            const float* f0 = sacc[2 * ks];
            const float* f1 = sacc[2 * ks + 1];
            uint32_t ph[4], pl[4];
            psplit2(f0[0], f0[1], ph[0], pl[0]);
            psplit2(f0[2], f0[3], ph[1], pl[1]);
            psplit2(f1[0], f1[1], ph[2], pl[2]);
            psplit2(f1[2], f1[3], ph[3], pl[3]);
            #pragma unroll
            for (int nfp = 0; nfp < 4; nfp++) {
                uint32_t vh4[4], vl4[4];
                uint32_t rv = sw128((ks * 16 + v4_r) * 128 + nfp * 32 + v4_n);
                ldmx4t(vstg + rv, vh4);
                ldmx4t(vstg + 8192 + rv, vl4);
                #pragma unroll
                for (int sub = 0; sub < 2; sub++) {
                    const int nf = nfp * 2 + sub;
                    mma16816(oacc[nf], ph, vh4 + sub * 2);
                    mma16816(oacc[nf], ph, vl4 + sub * 2);
                    mma16816(oacc[nf], pl, vh4 + sub * 2);
                }
            }
        }
    }

    // ---- epilogue: normalize, split, write ctx [B, L, D]
    const float inv0 = 1.0f / lrow[0];
    const float inv1 = 1.0f / lrow[1];
    const int lq0 = q0 + wid * 16 + gid;
    const size_t base0 = ((size_t)(bb * LQ + lq0)) * DD + hh * 64;
    const size_t base1 = ((size_t)(bb * LQ + lq0 + 8)) * DD + hh * 64;
    #pragma unroll
    for (int nf = 0; nf < 8; nf++) {
        const int col = nf * 8 + tig * 2;
        uint32_t hv, lv;
        psplit2(oacc[nf][0] * inv0, oacc[nf][1] * inv0, hv, lv);
        *(uint32_t*)&g_ctxh[base0 + col] = hv;
        *(uint32_t*)&g_ctxl[base0 + col] = lv;
        psplit2(oacc[nf][2] * inv1, oacc[nf][3] * inv1, hv, lv);
        *(uint32_t*)&g_ctxh[base1 + col] = hv;
        *(uint32_t*)&g_ctxl[base1 + col] = lv;
    }
}

// ---------------------------------------------------------------------------

extern "C" void kernel_launch(void* const* d_in, const int* in_sizes, int n_in,
                              void* d_out, int out_size) {
    const float* X   = (const float*)d_in[0];
    const float* Wq  = (const float*)d_in[1];
    const float* Wk  = (const float*)d_in[2];
    const float* Wv  = (const float*)d_in[3];
    const float* Wo  = (const float*)d_in[4];
    const float* bo  = (const float*)d_in[5];
    const float* Kbg = (const float*)d_in[6];
    const float* Vbg = (const float*)d_in[7];
    float* out = (float*)d_out;

    cudaFuncSetAttribute(mma_qkv, cudaFuncAttributeMaxDynamicSharedMemorySize, SM_GEMM);
    cudaFuncSetAttribute(mma_out, cudaFuncAttributeMaxDynamicSharedMemorySize, SM_GEMM);
    cudaFuncSetAttribute(attn_mma, cudaFuncAttributeMaxDynamicSharedMemorySize, SM_ATTN);

    split_x<<<MTOT * DD / 4 / 256, 256>>>(X);
    split_wT<<<dim3(DD / 32, DD / 32, 4), 256>>>(Wq, Wk, Wv, Wo);
    split_bg<<<dim3(BH * LQ * DHD / 4 / 256, 2), 256>>>(Kbg, Vbg);

    mma_qkv<<<dim3(DD / 128, MTOT / 128, 3), 256, SM_GEMM>>>();

    attn_mma<<<dim3(LQ / 128, BH), 256, SM_ATTN>>>();

    mma_out<<<dim3(DD / 128, MTOT / 128), 256, SM_GEMM>>>(bo, out);
}